// round 2
// baseline (speedup 1.0000x reference)
#include <cuda_runtime.h>
#include <math.h>

#define BB      4
#define LL      288
#define NNH     170
#define DDIM    128
#define NHEADS  8
#define WSZ     12
#define SHIFTSZ 6
#define HIDD    512
#define NWIN    24
#define MTOK    (BB * LL * NNH)   // 195840

// Scratch (static device globals — allocation-free)
__device__ float g_qkv[(size_t)MTOK * 384];   // (b,n,ls) x [q|k|v] heads-major
__device__ float g_attn[(size_t)MTOK * DDIM]; // (b,n,ls) attention output
__device__ float g_x1[(size_t)MTOK * DDIM];   // (b,n,l)  post-attn residual state
__device__ float g_h[(size_t)MTOK * HIDD];    // (b,n,l)  mlp hidden

// ---------------------------------------------------------------------------
// Tiled SGEMM, 128x128 block tile, BK=8, 256 threads, 8x8 per-thread microtile.
// MODE 0: A = gather(x, shift+transpose), out = qkv + bias          (K=128,N=384)
// MODE 1: A = g_attn, epilogue = unshift + LN1(g1,b1) + residual(x) (K=128,N=128)
// MODE 2: A = g_x1,   epilogue = GELU(.+bias)                       (K=128,N=512)
// MODE 3: A = g_h,    epilogue = LN2(g2,b2) + residual(g_x1),
//                     scatter to (B,L,N,D) output                   (K=512,N=128)
// ---------------------------------------------------------------------------
template<int MODE, int K, int NDIM>
__global__ __launch_bounds__(256)
void gemm_kernel(const float* __restrict__ W, const float* __restrict__ bias,
                 float* __restrict__ outp, const float* __restrict__ xin,
                 const float* __restrict__ gamma, const float* __restrict__ beta)
{
    __shared__ float As[8][128];
    __shared__ float Bs[8][128];

    const int tid = threadIdx.x;
    const int tx  = tid & 15;
    const int ty  = tid >> 4;
    const int rowBlock = blockIdx.x * 128;
    const int colBlock = blockIdx.y * 128;

    // A-tile loader assignment: row = tid/2, one float4 at k-offset (tid&1)*4
    const int la_row = tid >> 1;
    const int la_k   = (tid & 1) * 4;
    const int aRowG  = rowBlock + la_row;

    const float* arow;
    if (MODE == 0) {
        // row index space is (b, n, ls); gather from x (B,L,N,D) at l = ls - SHIFT
        int b   = aRowG / (NNH * LL);
        int rem = aRowG % (NNH * LL);
        int n   = rem / LL;
        int ls  = rem % LL;
        int l   = ls - SHIFTSZ; if (l < 0) l += LL;
        arow = xin + ((size_t)(b * LL + l) * NNH + n) * DDIM;
    } else if (MODE == 1) {
        arow = g_attn + (size_t)aRowG * K;
    } else if (MODE == 2) {
        arow = g_x1 + (size_t)aRowG * K;
    } else {
        arow = g_h + (size_t)aRowG * K;
    }

    // B-tile loader: row = tid/32 (0..7), col = (tid&31)*4
    const int lb_row = tid >> 5;
    const int lb_col = (tid & 31) * 4;

    float acc[8][8];
    #pragma unroll
    for (int i = 0; i < 8; i++)
        #pragma unroll
        for (int j = 0; j < 8; j++) acc[i][j] = 0.f;

    for (int k0 = 0; k0 < K; k0 += 8) {
        float4 av = *(const float4*)(arow + k0 + la_k);
        As[la_k + 0][la_row] = av.x;
        As[la_k + 1][la_row] = av.y;
        As[la_k + 2][la_row] = av.z;
        As[la_k + 3][la_row] = av.w;
        float4 bv = *(const float4*)(W + (size_t)(k0 + lb_row) * NDIM + colBlock + lb_col);
        *(float4*)(&Bs[lb_row][lb_col]) = bv;
        __syncthreads();
        #pragma unroll
        for (int kk = 0; kk < 8; kk++) {
            float ar[8], br[8];
            *(float4*)(ar)     = *(const float4*)(&As[kk][ty * 8]);
            *(float4*)(ar + 4) = *(const float4*)(&As[kk][ty * 8 + 4]);
            *(float4*)(br)     = *(const float4*)(&Bs[kk][tx * 8]);
            *(float4*)(br + 4) = *(const float4*)(&Bs[kk][tx * 8 + 4]);
            #pragma unroll
            for (int i = 0; i < 8; i++)
                #pragma unroll
                for (int j = 0; j < 8; j++)
                    acc[i][j] += ar[i] * br[j];
        }
        __syncthreads();
    }

    // bias
    #pragma unroll
    for (int j = 0; j < 8; j++) {
        float bj = bias[colBlock + tx * 8 + j];
        #pragma unroll
        for (int i = 0; i < 8; i++) acc[i][j] += bj;
    }

    if (MODE == 0) {
        #pragma unroll
        for (int i = 0; i < 8; i++) {
            int r = rowBlock + ty * 8 + i;
            float* dst = g_qkv + (size_t)r * 384 + colBlock + tx * 8;
            *(float4*)(dst)     = make_float4(acc[i][0], acc[i][1], acc[i][2], acc[i][3]);
            *(float4*)(dst + 4) = make_float4(acc[i][4], acc[i][5], acc[i][6], acc[i][7]);
        }
        return;
    }
    if (MODE == 2) {
        #pragma unroll
        for (int i = 0; i < 8; i++) {
            int r = rowBlock + ty * 8 + i;
            float* dst = g_h + (size_t)r * HIDD + colBlock + tx * 8;
            float v[8];
            #pragma unroll
            for (int j = 0; j < 8; j++) { float a = acc[i][j]; v[j] = a * normcdff(a); }
            *(float4*)(dst)     = make_float4(v[0], v[1], v[2], v[3]);
            *(float4*)(dst + 4) = make_float4(v[4], v[5], v[6], v[7]);
        }
        return;
    }

    if (MODE == 1 || MODE == 3) {
        // LayerNorm over the full 128-wide row (one CTA owns the whole row).
        __shared__ float ps [128][17];
        __shared__ float ps2[128][17];
        #pragma unroll
        for (int i = 0; i < 8; i++) {
            float s = 0.f, s2 = 0.f;
            #pragma unroll
            for (int j = 0; j < 8; j++) { s += acc[i][j]; s2 += acc[i][j] * acc[i][j]; }
            ps [ty * 8 + i][tx] = s;
            ps2[ty * 8 + i][tx] = s2;
        }
        __syncthreads();
        #pragma unroll
        for (int i = 0; i < 8; i++) {
            int lr = ty * 8 + i;
            float s = 0.f, s2 = 0.f;
            #pragma unroll
            for (int t = 0; t < 16; t++) { s += ps[lr][t]; s2 += ps2[lr][t]; }
            float mean = s  * (1.f / 128.f);
            float var  = s2 * (1.f / 128.f) - mean * mean;
            var = fmaxf(var, 0.f);
            float rstd = rsqrtf(var + 1e-5f);
            int r = rowBlock + lr;

            if (MODE == 1) {
                // row space (b,n,ls) -> output row (b,n,lo) with lo = ls - SHIFT
                int b   = r / (NNH * LL);
                int rem = r % (NNH * LL);
                int n   = rem / LL;
                int ls  = rem % LL;
                int lo  = ls - SHIFTSZ; if (lo < 0) lo += LL;
                const float* res = xin + ((size_t)(b * LL + lo) * NNH + n) * DDIM + tx * 8;
                float* dst = g_x1 + ((size_t)(b * NNH + n) * LL + lo) * DDIM + tx * 8;
                #pragma unroll
                for (int j = 0; j < 8; j++) {
                    int col = tx * 8 + j;
                    dst[j] = (acc[i][j] - mean) * rstd * gamma[col] + beta[col] + res[j];
                }
            } else {
                // row space (b,n,l); residual = g_x1; scatter to (B,L,N,D)
                int b   = r / (NNH * LL);
                int rem = r % (NNH * LL);
                int n   = rem / LL;
                int l   = rem % LL;
                const float* res = g_x1 + (size_t)r * DDIM + tx * 8;
                float* dst = outp + ((size_t)(b * LL + l) * NNH + n) * DDIM + tx * 8;
                #pragma unroll
                for (int j = 0; j < 8; j++) {
                    int col = tx * 8 + j;
                    dst[j] = (acc[i][j] - mean) * rstd * gamma[col] + beta[col] + res[j];
                }
            }
        }
    }
}

// ---------------------------------------------------------------------------
// Windowed attention: one block per (b, n, window). 96 threads = (head, row).
// qkv tile (12 x 384) staged in smem. Mask only nontrivial for window 0.
// ---------------------------------------------------------------------------
__global__ __launch_bounds__(96)
void attn_kernel()
{
    __shared__ float s[12 * 384];

    int blk = blockIdx.x;
    int w   = blk % NWIN;
    int rem = blk / NWIN;
    int n   = rem % NNH;
    int b   = rem / NNH;
    size_t base = (size_t)(b * NNH + n) * LL + w * WSZ;

    int tid = threadIdx.x;
    // 12 rows * 96 float4 per row = 1152 float4, 12 each
    for (int v = tid; v < 12 * 96; v += 96) {
        int i = v / 96, c = v % 96;
        *(float4*)(&s[i * 384 + c * 4]) = *(const float4*)(g_qkv + (base + i) * 384 + c * 4);
    }
    __syncthreads();

    int h = tid / 12;
    int i = tid % 12;
    const float* q = &s[i * 384 + h * 16];
    bool gi = (i < SHIFTSZ);

    float sc[12];
    float mx = -1e30f;
    #pragma unroll
    for (int j = 0; j < 12; j++) {
        const float* kp = &s[j * 384 + 128 + h * 16];
        float a = 0.f;
        #pragma unroll
        for (int d = 0; d < 16; d++) a += q[d] * kp[d];
        a *= 0.25f;                                     // SCALE = 16^-0.5
        if (w == 0 && (gi != (j < SHIFTSZ))) a -= 100.f; // swin shift mask
        sc[j] = a;
        mx = fmaxf(mx, a);
    }
    float den = 0.f;
    #pragma unroll
    for (int j = 0; j < 12; j++) { sc[j] = expf(sc[j] - mx); den += sc[j]; }
    float inv = 1.f / den;

    float o[16];
    #pragma unroll
    for (int d = 0; d < 16; d++) o[d] = 0.f;
    #pragma unroll
    for (int j = 0; j < 12; j++) {
        float p = sc[j] * inv;
        const float* vp = &s[j * 384 + 256 + h * 16];
        #pragma unroll
        for (int d = 0; d < 16; d++) o[d] += p * vp[d];
    }

    float* dst = g_attn + (base + i) * DDIM + h * 16;
    #pragma unroll
    for (int d = 0; d < 16; d++) dst[d] = o[d];
}

// ---------------------------------------------------------------------------
extern "C" void kernel_launch(void* const* d_in, const int* in_sizes, int n_in,
                              void* d_out, int out_size)
{
    const float* x      = (const float*)d_in[0];
    const float* qkv_w  = (const float*)d_in[1];
    const float* qkv_b  = (const float*)d_in[2];
    const float* proj_w = (const float*)d_in[3];
    const float* proj_b = (const float*)d_in[4];
    const float* fc1_w  = (const float*)d_in[5];
    const float* fc1_b  = (const float*)d_in[6];
    const float* fc2_w  = (const float*)d_in[7];
    const float* fc2_b  = (const float*)d_in[8];
    const float* g1     = (const float*)d_in[9];
    const float* b1     = (const float*)d_in[10];
    const float* g2     = (const float*)d_in[11];
    const float* b2     = (const float*)d_in[12];
    float* out = (float*)d_out;

    dim3 blk(256);
    const int MB = MTOK / 128; // 1530

    // 1) QKV projection (shift+transpose gather fused into A load)
    gemm_kernel<0, 128, 384><<<dim3(MB, 3), blk>>>(qkv_w, qkv_b, nullptr, x, nullptr, nullptr);
    // 2) windowed attention
    attn_kernel<<<BB * NNH * NWIN, 96>>>();
    // 3) proj + unshift + LN1 + residual(x)
    gemm_kernel<1, 128, 128><<<dim3(MB, 1), blk>>>(proj_w, proj_b, nullptr, x, g1, b1);
    // 4) fc1 + GELU
    gemm_kernel<2, 128, 512><<<dim3(MB, 4), blk>>>(fc1_w, fc1_b, nullptr, nullptr, nullptr, nullptr);
    // 5) fc2 + LN2 + residual(x1) + scatter to (B,L,N,D)
    gemm_kernel<3, 512, 128><<<dim3(MB, 1), blk>>>(fc2_w, fc2_b, out, nullptr, g2, b2);
}

// round 4
// speedup vs baseline: 1.6751x; 1.6751x over previous
#include <cuda_runtime.h>
#include <cuda_bf16.h>
#include <math.h>
#include <stdint.h>

#define BB      4
#define LL      288
#define NNH     170
#define DDIM    128
#define WSZ     12
#define SHIFTSZ 6
#define HIDD    512
#define NWIN    24
#define MTOK    (BB * LL * NNH)   // 195840

// ---------------- scratch (hi/lo bf16 split planes) ----------------
__device__ __align__(256) __nv_bfloat16 g_qkv_hi[(size_t)MTOK * 384];
__device__ __align__(256) __nv_bfloat16 g_qkv_lo[(size_t)MTOK * 384];
__device__ __align__(256) __nv_bfloat16 g_attn_hi[(size_t)MTOK * 128];
__device__ __align__(256) __nv_bfloat16 g_attn_lo[(size_t)MTOK * 128];
__device__ __align__(256) __nv_bfloat16 g_x1_hi[(size_t)MTOK * 128];
__device__ __align__(256) __nv_bfloat16 g_x1_lo[(size_t)MTOK * 128];
__device__ __align__(256) __nv_bfloat16 g_h_hi[(size_t)MTOK * 512];
__device__ __align__(256) __nv_bfloat16 g_h_lo[(size_t)MTOK * 512];
// transposed weights [N][K], hi/lo
#define OFF_QKV  0
#define OFF_PROJ 49152
#define OFF_FC1  65536
#define OFF_FC2  131072
#define W_TOTAL  196608
__device__ __align__(256) __nv_bfloat16 g_w_hi[W_TOTAL];
__device__ __align__(256) __nv_bfloat16 g_w_lo[W_TOTAL];

__device__ __forceinline__ uint32_t smem_u32(const void* p) {
    uint32_t a;
    asm("{ .reg .u64 t; cvta.to.shared.u64 t, %1; cvt.u32.u64 %0, t; }" : "=r"(a) : "l"(p));
    return a;
}
__device__ __forceinline__ void split_bf16(float v, __nv_bfloat16& h, __nv_bfloat16& l) {
    h = __float2bfloat16(v);
    l = __float2bfloat16(v - __bfloat162float(h));
}
__device__ __forceinline__ void ldm4(uint32_t* r, uint32_t addr) {
    asm volatile("ldmatrix.sync.aligned.m8n8.x4.shared.b16 {%0,%1,%2,%3}, [%4];"
        : "=r"(r[0]), "=r"(r[1]), "=r"(r[2]), "=r"(r[3]) : "r"(addr));
}
__device__ __forceinline__ void mma16816(float* d, const uint32_t* a, uint32_t b0, uint32_t b1) {
    asm volatile("mma.sync.aligned.m16n8k16.row.col.f32.bf16.bf16.f32 "
        "{%0,%1,%2,%3}, {%4,%5,%6,%7}, {%8,%9}, {%0,%1,%2,%3};"
        : "+f"(d[0]), "+f"(d[1]), "+f"(d[2]), "+f"(d[3])
        : "r"(a[0]), "r"(a[1]), "r"(a[2]), "r"(a[3]), "r"(b0), "r"(b1));
}

// smem tile layout: 128 rows x 64 bf16, padded to 144 B per row (conflict-free LDSM)
#define SROWB   144
#define PLANE   (128 * SROWB)     // 18432 B
#define SM_A_HI 0
#define SM_A_LO PLANE
#define SM_B_HI (2 * PLANE)
#define SM_B_LO (3 * PLANE)
#define SMEM_TOTAL (4 * PLANE)    // 73728 B (>= 128*132*4 fp32 epi buffer)

// ---------------------------------------------------------------------------
// HMMA GEMM, 128x128 CTA tile, K chunks of 64, bf16 hi/lo split (3 passes).
// MODE 0: A = gather(x, shift+transpose) fp32 -> qkv planes     (K=128, N=384)
// MODE 1: A = attn planes; epi = unshift + LN1 + residual(x)    (K=128, N=128)
// MODE 2: A = x1 planes;   epi = GELU -> h planes               (K=128, N=512)
// MODE 3: A = h planes;    epi = LN2 + residual(x1) -> out fp32 (K=512, N=128)
// ---------------------------------------------------------------------------
template<int MODE, int K>
__global__ __launch_bounds__(256, 2)
void tc_gemm(int woff, const float* __restrict__ bias, float* __restrict__ outp,
             const float* __restrict__ xin, const float* __restrict__ gamma,
             const float* __restrict__ beta)
{
    extern __shared__ __align__(1024) char smem[];
    const uint32_t sb = smem_u32(smem);
    const int tid = threadIdx.x;
    const int lane = tid & 31;
    const int wid = tid >> 5;
    const int wm = wid & 1;        // 2 m-blocks of 64
    const int wn = wid >> 1;       // 4 n-blocks of 32
    const int rowBlock = blockIdx.x * 128;
    const int colBlock = blockIdx.y * 128;

    // ---- loader assignment: chunk = tid&7 (16B), rows = (tid>>3) + i*32 ----
    const int lchunk = tid & 7;                 // 8 halves = 16B
    const int lrow0  = tid >> 3;                // + i*32, i in 0..3

    // per-row global sources
    const float* arow_f[4];
    const __nv_bfloat16 *ah_g[4], *al_g[4], *bh_g[4], *bl_g[4];
    #pragma unroll
    for (int i = 0; i < 4; i++) {
        int lr = lrow0 + i * 32;
        int gr = rowBlock + lr;
        if (MODE == 0) {
            int b = gr / (NNH * LL), rem = gr % (NNH * LL);
            int n = rem / LL, ls = rem % LL;
            int l = ls - SHIFTSZ; if (l < 0) l += LL;
            arow_f[i] = xin + ((size_t)(b * LL + l) * NNH + n) * DDIM;
        } else if (MODE == 1) {
            ah_g[i] = g_attn_hi + (size_t)gr * K;
            al_g[i] = g_attn_lo + (size_t)gr * K;
        } else if (MODE == 2) {
            ah_g[i] = g_x1_hi + (size_t)gr * K;
            al_g[i] = g_x1_lo + (size_t)gr * K;
        } else {
            ah_g[i] = g_h_hi + (size_t)gr * K;
            al_g[i] = g_h_lo + (size_t)gr * K;
        }
        bh_g[i] = g_w_hi + woff + (size_t)(colBlock + lr) * K;
        bl_g[i] = g_w_lo + woff + (size_t)(colBlock + lr) * K;
    }

    // ldmatrix row/col addressing (constant parts)
    const int lmRow = lane & 15;
    const uint32_t lmColB = (uint32_t)((lane >> 4) * 8) * 2;   // byte offset of k-subcol
    uint32_t aRowAddr[4], bRowAddr[2];
    #pragma unroll
    for (int mt = 0; mt < 4; mt++)
        aRowAddr[mt] = (uint32_t)(wm * 64 + mt * 16 + lmRow) * SROWB;
    #pragma unroll
    for (int pt = 0; pt < 2; pt++)
        bRowAddr[pt] = (uint32_t)(wn * 32 + pt * 16 + lmRow) * SROWB;

    float acc[4][4][4];
    #pragma unroll
    for (int mt = 0; mt < 4; mt++)
        #pragma unroll
        for (int nt = 0; nt < 4; nt++)
            #pragma unroll
            for (int e = 0; e < 4; e++) acc[mt][nt][e] = 0.f;

    constexpr int NC = K / 64;
    for (int ch = 0; ch < NC; ch++) {
        if (ch > 0) __syncthreads();
        const int k0 = ch * 64;
        const int kc = k0 + lchunk * 8;
        #pragma unroll
        for (int i = 0; i < 4; i++) {
            const int lr = lrow0 + i * 32;
            const uint32_t so = (uint32_t)lr * SROWB + (uint32_t)lchunk * 16;
            if (MODE == 0) {
                float4 f0 = *(const float4*)(arow_f[i] + kc);
                float4 f1 = *(const float4*)(arow_f[i] + kc + 4);
                float f[8] = {f0.x, f0.y, f0.z, f0.w, f1.x, f1.y, f1.z, f1.w};
                __align__(16) __nv_bfloat16 hv[8], lv[8];
                #pragma unroll
                for (int e = 0; e < 8; e++) split_bf16(f[e], hv[e], lv[e]);
                *(uint4*)(smem + SM_A_HI + so) = *(uint4*)hv;
                *(uint4*)(smem + SM_A_LO + so) = *(uint4*)lv;
            } else {
                *(uint4*)(smem + SM_A_HI + so) = *(const uint4*)(ah_g[i] + kc);
                *(uint4*)(smem + SM_A_LO + so) = *(const uint4*)(al_g[i] + kc);
            }
            *(uint4*)(smem + SM_B_HI + so) = *(const uint4*)(bh_g[i] + kc);
            *(uint4*)(smem + SM_B_LO + so) = *(const uint4*)(bl_g[i] + kc);
        }
        __syncthreads();

        #pragma unroll
        for (int kk = 0; kk < 4; kk++) {
            const uint32_t cb = (uint32_t)(kk * 16) * 2 + lmColB;
            uint32_t ahf[4][4], alf[4][4], bxf[2][4];
            // hi A frags + hi B frags -> hi*hi
            #pragma unroll
            for (int mt = 0; mt < 4; mt++) ldm4(ahf[mt], sb + SM_A_HI + aRowAddr[mt] + cb);
            #pragma unroll
            for (int pt = 0; pt < 2; pt++) ldm4(bxf[pt], sb + SM_B_HI + bRowAddr[pt] + cb);
            #pragma unroll
            for (int mt = 0; mt < 4; mt++)
                #pragma unroll
                for (int nt = 0; nt < 4; nt++)
                    mma16816(acc[mt][nt], ahf[mt], bxf[nt >> 1][nt & 1], bxf[nt >> 1][(nt & 1) + 2]);
            // lo A frags -> lo*hi
            #pragma unroll
            for (int mt = 0; mt < 4; mt++) ldm4(alf[mt], sb + SM_A_LO + aRowAddr[mt] + cb);
            #pragma unroll
            for (int mt = 0; mt < 4; mt++)
                #pragma unroll
                for (int nt = 0; nt < 4; nt++)
                    mma16816(acc[mt][nt], alf[mt], bxf[nt >> 1][nt & 1], bxf[nt >> 1][(nt & 1) + 2]);
            // lo B frags -> hi*lo
            #pragma unroll
            for (int pt = 0; pt < 2; pt++) ldm4(bxf[pt], sb + SM_B_LO + bRowAddr[pt] + cb);
            #pragma unroll
            for (int mt = 0; mt < 4; mt++)
                #pragma unroll
                for (int nt = 0; nt < 4; nt++)
                    mma16816(acc[mt][nt], ahf[mt], bxf[nt >> 1][nt & 1], bxf[nt >> 1][(nt & 1) + 2]);
        }
    }

    // ---------------- epilogue ----------------
    if (MODE == 0 || MODE == 2) {
        // direct store of acc (+bias, +GELU for MODE 2) as hi/lo planes
        const int ldst = (MODE == 0) ? 384 : 512;
        #pragma unroll
        for (int mt = 0; mt < 4; mt++) {
            const int r0 = rowBlock + wm * 64 + mt * 16 + (lane >> 2);
            #pragma unroll
            for (int nt = 0; nt < 4; nt++) {
                const int c = colBlock + wn * 32 + nt * 8 + (lane & 3) * 2;
                const float b0 = bias[c], b1 = bias[c + 1];
                #pragma unroll
                for (int half = 0; half < 2; half++) {
                    const int r = r0 + half * 8;
                    float v0 = acc[mt][nt][half * 2 + 0] + b0;
                    float v1 = acc[mt][nt][half * 2 + 1] + b1;
                    if (MODE == 2) { v0 = v0 * normcdff(v0); v1 = v1 * normcdff(v1); }
                    __nv_bfloat16 h0, l0, h1, l1;
                    split_bf16(v0, h0, l0);
                    split_bf16(v1, h1, l1);
                    __nv_bfloat16 *dh, *dl;
                    if (MODE == 0) { dh = g_qkv_hi; dl = g_qkv_lo; }
                    else           { dh = g_h_hi;   dl = g_h_lo;   }
                    *(__nv_bfloat162*)(dh + (size_t)r * ldst + c) = __nv_bfloat162(h0, h1);
                    *(__nv_bfloat162*)(dl + (size_t)r * ldst + c) = __nv_bfloat162(l0, l1);
                }
            }
        }
        return;
    }

    // LN modes: stage acc(+bias) into smem fp32 [128][132], then per-row LN
    __syncthreads();                 // tiles fully consumed; reuse smem
    float* sf = (float*)smem;        // pitch 132 floats
    #pragma unroll
    for (int mt = 0; mt < 4; mt++) {
        const int r0 = wm * 64 + mt * 16 + (lane >> 2);
        #pragma unroll
        for (int nt = 0; nt < 4; nt++) {
            const int c = wn * 32 + nt * 8 + (lane & 3) * 2;
            const float b0 = bias[c], b1 = bias[c + 1];
            sf[(r0)     * 132 + c]     = acc[mt][nt][0] + b0;
            sf[(r0)     * 132 + c + 1] = acc[mt][nt][1] + b1;
            sf[(r0 + 8) * 132 + c]     = acc[mt][nt][2] + b0;
            sf[(r0 + 8) * 132 + c + 1] = acc[mt][nt][3] + b1;
        }
    }
    __syncthreads();

    if (tid < 128) {
        const int r = rowBlock + tid;
        const float* row = sf + tid * 132;
        float s = 0.f, s2 = 0.f;
        #pragma unroll 16
        for (int c = 0; c < 128; c++) { float v = row[c]; s += v; s2 += v * v; }
        const float mean = s * (1.f / 128.f);
        const float var = fmaxf(s2 * (1.f / 128.f) - mean * mean, 0.f);
        const float rstd = rsqrtf(var + 1e-5f);

        int b = r / (NNH * LL), rem = r % (NNH * LL);
        int n = rem / LL, li = rem % LL;

        if (MODE == 1) {
            int lo_ = li - SHIFTSZ; if (lo_ < 0) lo_ += LL;
            const float* resf = xin + ((size_t)(b * LL + lo_) * NNH + n) * DDIM;
            size_t orow = ((size_t)(b * NNH + n) * LL + lo_) * DDIM;
            __nv_bfloat16* dh = g_x1_hi + orow;
            __nv_bfloat16* dl = g_x1_lo + orow;
            for (int c = 0; c < 128; c += 2) {
                float y0 = (row[c]     - mean) * rstd * gamma[c]     + beta[c]     + resf[c];
                float y1 = (row[c + 1] - mean) * rstd * gamma[c + 1] + beta[c + 1] + resf[c + 1];
                __nv_bfloat16 h0, l0, h1, l1;
                split_bf16(y0, h0, l0);
                split_bf16(y1, h1, l1);
                *(__nv_bfloat162*)(dh + c) = __nv_bfloat162(h0, h1);
                *(__nv_bfloat162*)(dl + c) = __nv_bfloat162(l0, l1);
            }
        } else {
            const __nv_bfloat16* rh = g_x1_hi + (size_t)r * 128;
            const __nv_bfloat16* rl = g_x1_lo + (size_t)r * 128;
            float* dst = outp + ((size_t)(b * LL + li) * NNH + n) * DDIM;
            for (int c = 0; c < 128; c += 4) {
                float4 o;
                float res0 = __bfloat162float(rh[c])     + __bfloat162float(rl[c]);
                float res1 = __bfloat162float(rh[c + 1]) + __bfloat162float(rl[c + 1]);
                float res2 = __bfloat162float(rh[c + 2]) + __bfloat162float(rl[c + 2]);
                float res3 = __bfloat162float(rh[c + 3]) + __bfloat162float(rl[c + 3]);
                o.x = (row[c]     - mean) * rstd * gamma[c]     + beta[c]     + res0;
                o.y = (row[c + 1] - mean) * rstd * gamma[c + 1] + beta[c + 1] + res1;
                o.z = (row[c + 2] - mean) * rstd * gamma[c + 2] + beta[c + 2] + res2;
                o.w = (row[c + 3] - mean) * rstd * gamma[c + 3] + beta[c + 3] + res3;
                *(float4*)(dst + c) = o;
            }
        }
    }
}

// ---------------------------------------------------------------------------
// Weight prep: fp32 [K][N] -> transposed bf16 hi/lo [N][K]
// ---------------------------------------------------------------------------
__global__ void prep_w(const float* __restrict__ qkv_w, const float* __restrict__ proj_w,
                       const float* __restrict__ fc1_w, const float* __restrict__ fc2_w)
{
    int idx = blockIdx.x * 256 + threadIdx.x;
    if (idx >= W_TOTAL) return;
    const float* src; int K, N, base;
    if (idx < OFF_PROJ)      { src = qkv_w;  K = 128; N = 384; base = OFF_QKV;  }
    else if (idx < OFF_FC1)  { src = proj_w; K = 128; N = 128; base = OFF_PROJ; }
    else if (idx < OFF_FC2)  { src = fc1_w;  K = 128; N = 512; base = OFF_FC1;  }
    else                     { src = fc2_w;  K = 512; N = 128; base = OFF_FC2;  }
    int local = idx - base;
    int nn = local / K, kk = local % K;
    float v = src[(size_t)kk * N + nn];
    __nv_bfloat16 h, l;
    split_bf16(v, h, l);
    g_w_hi[idx] = h;
    g_w_lo[idx] = l;
}

// ---------------------------------------------------------------------------
// Windowed attention: one block per (b, n, window). 96 threads = (head, row).
// ---------------------------------------------------------------------------
__global__ __launch_bounds__(96)
void attn_kernel()
{
    __shared__ float s[12 * 384];

    int blk = blockIdx.x;
    int w = blk % NWIN, rem = blk / NWIN;
    int n = rem % NNH, b = rem / NNH;
    size_t base = (size_t)(b * NNH + n) * LL + w * WSZ;

    int tid = threadIdx.x;
    for (int v = tid; v < 576; v += 96) {
        int i = v / 48, g = (v % 48) * 8;
        uint4 hv = *(const uint4*)(g_qkv_hi + (base + i) * 384 + g);
        uint4 lv = *(const uint4*)(g_qkv_lo + (base + i) * 384 + g);
        const __nv_bfloat16* hb = (const __nv_bfloat16*)&hv;
        const __nv_bfloat16* lb = (const __nv_bfloat16*)&lv;
        #pragma unroll
        for (int e = 0; e < 8; e++)
            s[i * 384 + g + e] = __bfloat162float(hb[e]) + __bfloat162float(lb[e]);
    }
    __syncthreads();

    int h = tid / 12;
    int i = tid % 12;
    const float* q = &s[i * 384 + h * 16];
    bool gi = (i < SHIFTSZ);

    float sc[12];
    float mx = -1e30f;
    #pragma unroll
    for (int j = 0; j < 12; j++) {
        const float* kp = &s[j * 384 + 128 + h * 16];
        float a = 0.f;
        #pragma unroll
        for (int d = 0; d < 16; d++) a += q[d] * kp[d];
        a *= 0.25f;
        if (w == 0 && (gi != (j < SHIFTSZ))) a -= 100.f;
        sc[j] = a;
        mx = fmaxf(mx, a);
    }
    float den = 0.f;
    #pragma unroll
    for (int j = 0; j < 12; j++) { sc[j] = expf(sc[j] - mx); den += sc[j]; }
    float inv = 1.f / den;

    float o[16];
    #pragma unroll
    for (int d = 0; d < 16; d++) o[d] = 0.f;
    #pragma unroll
    for (int j = 0; j < 12; j++) {
        float p = sc[j] * inv;
        const float* vp = &s[j * 384 + 256 + h * 16];
        #pragma unroll
        for (int d = 0; d < 16; d++) o[d] += p * vp[d];
    }

    __align__(16) __nv_bfloat16 hv[16], lv[16];
    #pragma unroll
    for (int d = 0; d < 16; d++) split_bf16(o[d], hv[d], lv[d]);
    __nv_bfloat16* dh = g_attn_hi + (base + i) * 128 + h * 16;
    __nv_bfloat16* dl = g_attn_lo + (base + i) * 128 + h * 16;
    *(uint4*)(dh) = *(uint4*)(hv);
    *(uint4*)(dh + 8) = *(uint4*)(hv + 8);
    *(uint4*)(dl) = *(uint4*)(lv);
    *(uint4*)(dl + 8) = *(uint4*)(lv + 8);
}

// ---------------------------------------------------------------------------
extern "C" void kernel_launch(void* const* d_in, const int* in_sizes, int n_in,
                              void* d_out, int out_size)
{
    const float* x      = (const float*)d_in[0];
    const float* qkv_w  = (const float*)d_in[1];
    const float* qkv_b  = (const float*)d_in[2];
    const float* proj_w = (const float*)d_in[3];
    const float* proj_b = (const float*)d_in[4];
    const float* fc1_w  = (const float*)d_in[5];
    const float* fc1_b  = (const float*)d_in[6];
    const float* fc2_w  = (const float*)d_in[7];
    const float* fc2_b  = (const float*)d_in[8];
    const float* g1     = (const float*)d_in[9];
    const float* b1     = (const float*)d_in[10];
    const float* g2     = (const float*)d_in[11];
    const float* b2     = (const float*)d_in[12];
    float* out = (float*)d_out;

    static bool attr_done = false;
    if (!attr_done) {
        cudaFuncSetAttribute(tc_gemm<0, 128>, cudaFuncAttributeMaxDynamicSharedMemorySize, SMEM_TOTAL);
        cudaFuncSetAttribute(tc_gemm<1, 128>, cudaFuncAttributeMaxDynamicSharedMemorySize, SMEM_TOTAL);
        cudaFuncSetAttribute(tc_gemm<2, 128>, cudaFuncAttributeMaxDynamicSharedMemorySize, SMEM_TOTAL);
        cudaFuncSetAttribute(tc_gemm<3, 512>, cudaFuncAttributeMaxDynamicSharedMemorySize, SMEM_TOTAL);
        attr_done = true;
    }

    const int MB = MTOK / 128; // 1530

    // 0) weight transpose + split
    prep_w<<<(W_TOTAL + 255) / 256, 256>>>(qkv_w, proj_w, fc1_w, fc2_w);
    // 1) QKV projection (shift+transpose gather fused into A load)
    tc_gemm<0, 128><<<dim3(MB, 3), 256, SMEM_TOTAL>>>(OFF_QKV, qkv_b, nullptr, x, nullptr, nullptr);
    // 2) windowed attention
    attn_kernel<<<BB * NNH * NWIN, 96>>>();
    // 3) proj + unshift + LN1 + residual(x)
    tc_gemm<1, 128><<<dim3(MB, 1), 256, SMEM_TOTAL>>>(OFF_PROJ, proj_b, nullptr, x, g1, b1);
    // 4) fc1 + GELU
    tc_gemm<2, 128><<<dim3(MB, 4), 256, SMEM_TOTAL>>>(OFF_FC1, fc1_b, nullptr, nullptr, nullptr, nullptr);
    // 5) fc2 + LN2 + residual(x1) + scatter to (B,L,N,D)
    tc_gemm<3, 512><<<dim3(MB, 1), 256, SMEM_TOTAL>>>(OFF_FC2, fc2_b, out, nullptr, g2, b2);
}

// round 5
// speedup vs baseline: 2.0798x; 1.2416x over previous
#include <cuda_runtime.h>
#include <cuda_fp16.h>
#include <math.h>
#include <stdint.h>

#define BB      4
#define LL      288
#define NNH     170
#define DDIM    128
#define WSZ     12
#define SHIFTSZ 6
#define HIDD    512
#define NWIN    24
#define MTOK    (BB * LL * NNH)   // 195840

// ---------------- scratch ----------------
__device__ __align__(256) __half g_qkv[(size_t)MTOK * 384];   // fp16 activations
__device__ __align__(256) __half g_attn[(size_t)MTOK * 128];
__device__ __align__(256) __half g_x1h[(size_t)MTOK * 128];   // x1 as GEMM input
__device__ __align__(256) float  g_x1f[(size_t)MTOK * 128];   // x1 exact (residual)
__device__ __align__(256) __half g_h[(size_t)MTOK * 512];
// transposed weights [N][K], fp16 hi/lo split
#define OFF_QKV  0
#define OFF_PROJ 49152
#define OFF_FC1  65536
#define OFF_FC2  131072
#define W_TOTAL  196608
__device__ __align__(256) __half g_w_hi[W_TOTAL];
__device__ __align__(256) __half g_w_lo[W_TOTAL];

// ---------------- helpers ----------------
__device__ __forceinline__ uint32_t smem_u32(const void* p) {
    uint32_t a;
    asm("{ .reg .u64 t; cvta.to.shared.u64 t, %1; cvt.u32.u64 %0, t; }" : "=r"(a) : "l"(p));
    return a;
}
__device__ __forceinline__ void ldm4(uint32_t* r, uint32_t addr) {
    asm volatile("ldmatrix.sync.aligned.m8n8.x4.shared.b16 {%0,%1,%2,%3}, [%4];"
        : "=r"(r[0]), "=r"(r[1]), "=r"(r[2]), "=r"(r[3]) : "r"(addr));
}
__device__ __forceinline__ void mma16816(float* d, const uint32_t* a, uint32_t b0, uint32_t b1) {
    asm volatile("mma.sync.aligned.m16n8k16.row.col.f32.f16.f16.f32 "
        "{%0,%1,%2,%3}, {%4,%5,%6,%7}, {%8,%9}, {%0,%1,%2,%3};"
        : "+f"(d[0]), "+f"(d[1]), "+f"(d[2]), "+f"(d[3])
        : "r"(a[0]), "r"(a[1]), "r"(a[2]), "r"(a[3]), "r"(b0), "r"(b1));
}
#define CP16(dst, src) \
    asm volatile("cp.async.cg.shared.global [%0], [%1], 16;" :: "r"(dst), "l"(src) : "memory")
#define CPCOMMIT() asm volatile("cp.async.commit_group;" ::: "memory")

// smem: per stage A(256x144B) + Bhi(128x144B) + Blo(128x144B), double buffered
#define SROWB   144
#define A_BYTES (256 * SROWB)              // 36864
#define B_BYTES (128 * SROWB)              // 18432
#define STAGE   (A_BYTES + 2 * B_BYTES)    // 73728
#define SMEM_TOTAL (2 * STAGE)             // 147456

// ---------------------------------------------------------------------------
// HMMA GEMM: CTA 256x128, 512 thr (16 warps 4m x 4n, warp 64x32), K-chunk 64,
// 2-stage cp.async pipeline, fp16 A x (fp16 hi + lo) B = 2 MMA passes.
// MODE 0: A = gather(x, shift+transpose) fp32->fp16 -> g_qkv     (K=128, N=384)
// MODE 1: A = g_attn; epi = unshift + LN1 + residual(x) -> x1   (K=128, N=128)
// MODE 2: A = g_x1h;  epi = GELU -> g_h                          (K=128, N=512)
// MODE 3: A = g_h;    epi = LN2 + residual(x1f) -> out fp32      (K=512, N=128)
// ---------------------------------------------------------------------------
template<int MODE, int K>
__global__ __launch_bounds__(512, 1)
void tc_gemm(int woff, const float* __restrict__ bias, float* __restrict__ outp,
             const float* __restrict__ xin, const float* __restrict__ gamma,
             const float* __restrict__ beta)
{
    extern __shared__ __align__(1024) char smem[];
    const uint32_t sb = smem_u32(smem);
    const int tid = threadIdx.x;
    const int lane = tid & 31;
    const int wid = tid >> 5;
    const int wm = wid & 3;        // 4 m-blocks of 64
    const int wn = wid >> 2;       // 4 n-blocks of 32
    const int rowBlock = blockIdx.x * 256;
    const int colBlock = blockIdx.y * 128;

    // loader: each thread owns chunk column (tid&7)*16B; A rows lrow+64j (j<4), B rows lrow+64j (j<2)
    const int lcc  = tid & 7;
    const int lrow = tid >> 3;     // 0..63

    const float* g0row[4];
    const __half* asrc = nullptr;
    if (MODE == 0) {
        #pragma unroll
        for (int j = 0; j < 4; j++) {
            int gr = rowBlock + lrow + 64 * j;
            int b = gr / (NNH * LL), rem = gr % (NNH * LL);
            int n = rem / LL, ls = rem % LL;
            int l = ls - SHIFTSZ; if (l < 0) l += LL;
            g0row[j] = xin + ((size_t)(b * LL + l) * NNH + n) * DDIM;
        }
    } else if (MODE == 1) asrc = g_attn;
    else if (MODE == 2) asrc = g_x1h;
    else asrc = g_h;

    const __half* whi = g_w_hi + woff;
    const __half* wlo = g_w_lo + woff;

    float acc[4][4][4];
    #pragma unroll
    for (int mt = 0; mt < 4; mt++)
        #pragma unroll
        for (int nt = 0; nt < 4; nt++)
            #pragma unroll
            for (int e = 0; e < 4; e++) acc[mt][nt][e] = 0.f;

    constexpr int NC = K / 64;

    // ---- stage loader ----
    auto load_stage = [&](int ch, int s) {
        const int k0 = ch * 64 + lcc * 8;
        const uint32_t so = (uint32_t)lrow * SROWB + (uint32_t)lcc * 16;
        const uint32_t sA = sb + (uint32_t)s * STAGE;
        // A rows
        #pragma unroll
        for (int j = 0; j < 4; j++) {
            uint32_t dst = sA + so + (uint32_t)(j * 64 * SROWB);
            if (MODE == 0) {
                float4 f0 = *(const float4*)(g0row[j] + k0);
                float4 f1 = *(const float4*)(g0row[j] + k0 + 4);
                __align__(16) __half hv[8];
                hv[0] = __float2half_rn(f0.x); hv[1] = __float2half_rn(f0.y);
                hv[2] = __float2half_rn(f0.z); hv[3] = __float2half_rn(f0.w);
                hv[4] = __float2half_rn(f1.x); hv[5] = __float2half_rn(f1.y);
                hv[6] = __float2half_rn(f1.z); hv[7] = __float2half_rn(f1.w);
                *(uint4*)(smem + (size_t)s * STAGE + lrow * SROWB + lcc * 16 + j * 64 * SROWB) = *(uint4*)hv;
            } else {
                const __half* src = asrc + (size_t)(rowBlock + lrow + 64 * j) * K + k0;
                CP16(dst, src);
            }
        }
        // B rows (hi + lo)
        #pragma unroll
        for (int j = 0; j < 2; j++) {
            const int nrow = lrow + 64 * j;
            const uint32_t bo = (uint32_t)nrow * SROWB + (uint32_t)lcc * 16;
            CP16(sA + A_BYTES + bo, whi + (size_t)(colBlock + nrow) * K + k0);
            CP16(sA + A_BYTES + B_BYTES + bo, wlo + (size_t)(colBlock + nrow) * K + k0);
        }
        CPCOMMIT();
    };

    const int lmRow = lane & 15;
    const uint32_t lmColB = (uint32_t)((lane >> 4) * 16);

    load_stage(0, 0);
    for (int ch = 0; ch < NC; ch++) {
        if (ch + 1 < NC) {
            load_stage(ch + 1, (ch + 1) & 1);
            asm volatile("cp.async.wait_group 1;" ::: "memory");
        } else {
            asm volatile("cp.async.wait_group 0;" ::: "memory");
        }
        __syncthreads();

        const uint32_t sA = sb + (uint32_t)(ch & 1) * STAGE;
        const uint32_t sBh = sA + A_BYTES;
        const uint32_t sBl = sBh + B_BYTES;
        #pragma unroll
        for (int kk = 0; kk < 4; kk++) {
            const uint32_t cb = (uint32_t)(kk * 32) + lmColB;
            uint32_t af[4][4], bf[2][4];
            #pragma unroll
            for (int mt = 0; mt < 4; mt++)
                ldm4(af[mt], sA + (uint32_t)(wm * 64 + mt * 16 + lmRow) * SROWB + cb);
            #pragma unroll
            for (int pt = 0; pt < 2; pt++)
                ldm4(bf[pt], sBh + (uint32_t)(wn * 32 + pt * 16 + lmRow) * SROWB + cb);
            #pragma unroll
            for (int mt = 0; mt < 4; mt++)
                #pragma unroll
                for (int nt = 0; nt < 4; nt++)
                    mma16816(acc[mt][nt], af[mt], bf[nt >> 1][nt & 1], bf[nt >> 1][(nt & 1) + 2]);
            #pragma unroll
            for (int pt = 0; pt < 2; pt++)
                ldm4(bf[pt], sBl + (uint32_t)(wn * 32 + pt * 16 + lmRow) * SROWB + cb);
            #pragma unroll
            for (int mt = 0; mt < 4; mt++)
                #pragma unroll
                for (int nt = 0; nt < 4; nt++)
                    mma16816(acc[mt][nt], af[mt], bf[nt >> 1][nt & 1], bf[nt >> 1][(nt & 1) + 2]);
        }
        __syncthreads();
    }

    // ---------------- epilogue ----------------
    if (MODE == 0 || MODE == 2) {
        const int ldst = (MODE == 0) ? 384 : 512;
        __half* base = (MODE == 0) ? g_qkv : g_h;
        #pragma unroll
        for (int mt = 0; mt < 4; mt++) {
            const int r0 = rowBlock + wm * 64 + mt * 16 + (lane >> 2);
            #pragma unroll
            for (int nt = 0; nt < 4; nt++) {
                const int c = colBlock + wn * 32 + nt * 8 + (lane & 3) * 2;
                const float b0 = bias[c], b1 = bias[c + 1];
                #pragma unroll
                for (int hh = 0; hh < 2; hh++) {
                    const int r = r0 + hh * 8;
                    float v0 = acc[mt][nt][hh * 2 + 0] + b0;
                    float v1 = acc[mt][nt][hh * 2 + 1] + b1;
                    if (MODE == 2) { v0 = v0 * normcdff(v0); v1 = v1 * normcdff(v1); }
                    *(__half2*)(base + (size_t)r * ldst + c) = __floats2half2_rn(v0, v1);
                }
            }
        }
        return;
    }

    // LN modes: stage acc(+bias) to smem fp32 [256][131], per-row LN
    float* sf = (float*)smem;  // pitch 131 floats (conflict-free column reads)
    #pragma unroll
    for (int mt = 0; mt < 4; mt++) {
        const int r0 = wm * 64 + mt * 16 + (lane >> 2);
        #pragma unroll
        for (int nt = 0; nt < 4; nt++) {
            const int c = wn * 32 + nt * 8 + (lane & 3) * 2;
            const float b0 = bias[c], b1 = bias[c + 1];
            sf[(r0)     * 131 + c]     = acc[mt][nt][0] + b0;
            sf[(r0)     * 131 + c + 1] = acc[mt][nt][1] + b1;
            sf[(r0 + 8) * 131 + c]     = acc[mt][nt][2] + b0;
            sf[(r0 + 8) * 131 + c + 1] = acc[mt][nt][3] + b1;
        }
    }
    __syncthreads();

    if (tid < 256) {
        const int r = rowBlock + tid;
        const float* row = sf + tid * 131;
        float s = 0.f, s2 = 0.f;
        #pragma unroll 16
        for (int c = 0; c < 128; c++) { float v = row[c]; s += v; s2 += v * v; }
        const float mean = s * (1.f / 128.f);
        const float var = fmaxf(s2 * (1.f / 128.f) - mean * mean, 0.f);
        const float rstd = rsqrtf(var + 1e-5f);

        int b = r / (NNH * LL), rem = r % (NNH * LL);
        int n = rem / LL, li = rem % LL;

        if (MODE == 1) {
            int lo_ = li - SHIFTSZ; if (lo_ < 0) lo_ += LL;
            const float* resf = xin + ((size_t)(b * LL + lo_) * NNH + n) * DDIM;
            size_t orow = ((size_t)(b * NNH + n) * LL + lo_) * DDIM;
            __half* dh = g_x1h + orow;
            float*  df = g_x1f + orow;
            for (int c = 0; c < 128; c += 2) {
                float y0 = (row[c]     - mean) * rstd * gamma[c]     + beta[c]     + resf[c];
                float y1 = (row[c + 1] - mean) * rstd * gamma[c + 1] + beta[c + 1] + resf[c + 1];
                *(__half2*)(dh + c) = __floats2half2_rn(y0, y1);
                df[c] = y0; df[c + 1] = y1;
            }
        } else {
            const float* resf = g_x1f + (size_t)r * 128;
            float* dst = outp + ((size_t)(b * LL + li) * NNH + n) * DDIM;
            for (int c = 0; c < 128; c += 4) {
                float4 o;
                o.x = (row[c]     - mean) * rstd * gamma[c]     + beta[c]     + resf[c];
                o.y = (row[c + 1] - mean) * rstd * gamma[c + 1] + beta[c + 1] + resf[c + 1];
                o.z = (row[c + 2] - mean) * rstd * gamma[c + 2] + beta[c + 2] + resf[c + 2];
                o.w = (row[c + 3] - mean) * rstd * gamma[c + 3] + beta[c + 3] + resf[c + 3];
                *(float4*)(dst + c) = o;
            }
        }
    }
}

// ---------------------------------------------------------------------------
// Weight prep: fp32 [K][N] -> transposed fp16 hi/lo [N][K]
// ---------------------------------------------------------------------------
__global__ void prep_w(const float* __restrict__ qkv_w, const float* __restrict__ proj_w,
                       const float* __restrict__ fc1_w, const float* __restrict__ fc2_w)
{
    int idx = blockIdx.x * 256 + threadIdx.x;
    if (idx >= W_TOTAL) return;
    const float* src; int K, N, base;
    if (idx < OFF_PROJ)      { src = qkv_w;  K = 128; N = 384; base = OFF_QKV;  }
    else if (idx < OFF_FC1)  { src = proj_w; K = 128; N = 128; base = OFF_PROJ; }
    else if (idx < OFF_FC2)  { src = fc1_w;  K = 128; N = 512; base = OFF_FC1;  }
    else                     { src = fc2_w;  K = 512; N = 128; base = OFF_FC2;  }
    int local = idx - base;
    int nn = local / K, kk = local % K;
    float v = src[(size_t)kk * N + nn];
    __half h = __float2half_rn(v);
    g_w_hi[idx] = h;
    g_w_lo[idx] = __float2half_rn(v - __half2float(h));
}

// ---------------------------------------------------------------------------
// Windowed attention: one block per (b, n, window). 96 threads = (head, row).
// ---------------------------------------------------------------------------
__global__ __launch_bounds__(96)
void attn_kernel()
{
    __shared__ float s[12 * 384];

    int blk = blockIdx.x;
    int w = blk % NWIN, rem = blk / NWIN;
    int n = rem % NNH, b = rem / NNH;
    size_t base = (size_t)(b * NNH + n) * LL + w * WSZ;

    int tid = threadIdx.x;
    for (int v = tid; v < 576; v += 96) {
        int i = v / 48, g = (v % 48) * 8;
        uint4 hv = *(const uint4*)(g_qkv + (base + i) * 384 + g);
        const __half* hb = (const __half*)&hv;
        #pragma unroll
        for (int e = 0; e < 8; e++) s[i * 384 + g + e] = __half2float(hb[e]);
    }
    __syncthreads();

    int h = tid / 12;
    int i = tid % 12;
    const float* q = &s[i * 384 + h * 16];
    bool gi = (i < SHIFTSZ);

    float sc[12];
    float mx = -1e30f;
    #pragma unroll
    for (int j = 0; j < 12; j++) {
        const float* kp = &s[j * 384 + 128 + h * 16];
        float a = 0.f;
        #pragma unroll
        for (int d = 0; d < 16; d++) a += q[d] * kp[d];
        a *= 0.25f;
        if (w == 0 && (gi != (j < SHIFTSZ))) a -= 100.f;
        sc[j] = a;
        mx = fmaxf(mx, a);
    }
    float den = 0.f;
    #pragma unroll
    for (int j = 0; j < 12; j++) { sc[j] = expf(sc[j] - mx); den += sc[j]; }
    float inv = 1.f / den;

    float o[16];
    #pragma unroll
    for (int d = 0; d < 16; d++) o[d] = 0.f;
    #pragma unroll
    for (int j = 0; j < 12; j++) {
        float p = sc[j] * inv;
        const float* vp = &s[j * 384 + 256 + h * 16];
        #pragma unroll
        for (int d = 0; d < 16; d++) o[d] += p * vp[d];
    }

    __align__(16) __half hv[16];
    #pragma unroll
    for (int d = 0; d < 16; d++) hv[d] = __float2half_rn(o[d]);
    __half* dst = g_attn + (base + i) * 128 + h * 16;
    *(uint4*)(dst)     = *(uint4*)(hv);
    *(uint4*)(dst + 8) = *(uint4*)(hv + 8);
}

// ---------------------------------------------------------------------------
extern "C" void kernel_launch(void* const* d_in, const int* in_sizes, int n_in,
                              void* d_out, int out_size)
{
    const float* x      = (const float*)d_in[0];
    const float* qkv_w  = (const float*)d_in[1];
    const float* qkv_b  = (const float*)d_in[2];
    const float* proj_w = (const float*)d_in[3];
    const float* proj_b = (const float*)d_in[4];
    const float* fc1_w  = (const float*)d_in[5];
    const float* fc1_b  = (const float*)d_in[6];
    const float* fc2_w  = (const float*)d_in[7];
    const float* fc2_b  = (const float*)d_in[8];
    const float* g1     = (const float*)d_in[9];
    const float* b1     = (const float*)d_in[10];
    const float* g2     = (const float*)d_in[11];
    const float* b2     = (const float*)d_in[12];
    float* out = (float*)d_out;

    static bool attr_done = false;
    if (!attr_done) {
        cudaFuncSetAttribute(tc_gemm<0, 128>, cudaFuncAttributeMaxDynamicSharedMemorySize, SMEM_TOTAL);
        cudaFuncSetAttribute(tc_gemm<1, 128>, cudaFuncAttributeMaxDynamicSharedMemorySize, SMEM_TOTAL);
        cudaFuncSetAttribute(tc_gemm<2, 128>, cudaFuncAttributeMaxDynamicSharedMemorySize, SMEM_TOTAL);
        cudaFuncSetAttribute(tc_gemm<3, 512>, cudaFuncAttributeMaxDynamicSharedMemorySize, SMEM_TOTAL);
        attr_done = true;
    }

    const int MB = MTOK / 256; // 765

    // 0) weight transpose + fp16 hi/lo split
    prep_w<<<(W_TOTAL + 255) / 256, 256>>>(qkv_w, proj_w, fc1_w, fc2_w);
    // 1) QKV projection (shift+transpose gather fused into A load)
    tc_gemm<0, 128><<<dim3(MB, 3), 512, SMEM_TOTAL>>>(OFF_QKV, qkv_b, nullptr, x, nullptr, nullptr);
    // 2) windowed attention
    attn_kernel<<<BB * NNH * NWIN, 96>>>();
    // 3) proj + unshift + LN1 + residual(x)
    tc_gemm<1, 128><<<dim3(MB, 1), 512, SMEM_TOTAL>>>(OFF_PROJ, proj_b, nullptr, x, g1, b1);
    // 4) fc1 + GELU
    tc_gemm<2, 128><<<dim3(MB, 4), 512, SMEM_TOTAL>>>(OFF_FC1, fc1_b, nullptr, nullptr, nullptr, nullptr);
    // 5) fc2 + LN2 + residual(x1) + scatter to (B,L,N,D)
    tc_gemm<3, 512><<<dim3(MB, 1), 512, SMEM_TOTAL>>>(OFF_FC2, fc2_b, out, nullptr, g2, b2);
}

// round 6
// speedup vs baseline: 2.8819x; 1.3856x over previous
#include <cuda_runtime.h>
#include <cuda_fp16.h>
#include <math.h>
#include <stdint.h>

#define BB      4
#define LL      288
#define NNH     170
#define DDIM    128
#define WSZ     12
#define SHIFTSZ 6
#define HIDD    512
#define NWIN    24
#define MTOK    (BB * LL * NNH)   // 195840

// ---------------- scratch (fp16 activations, single plane) ----------------
__device__ __align__(256) __half g_qkv[(size_t)MTOK * 384];
__device__ __align__(256) __half g_attn[(size_t)MTOK * 128];
__device__ __align__(256) __half g_x1h[(size_t)MTOK * 128];
__device__ __align__(256) __half g_h[(size_t)MTOK * 512];
// transposed weights [N][K], fp16
#define OFF_QKV  0
#define OFF_PROJ 49152
#define OFF_FC1  65536
#define OFF_FC2  131072
#define W_TOTAL  196608
__device__ __align__(256) __half g_w[W_TOTAL];

// ---------------- helpers ----------------
__device__ __forceinline__ uint32_t smem_u32(const void* p) {
    uint32_t a;
    asm("{ .reg .u64 t; cvta.to.shared.u64 t, %1; cvt.u32.u64 %0, t; }" : "=r"(a) : "l"(p));
    return a;
}
__device__ __forceinline__ void ldm4(uint32_t* r, uint32_t addr) {
    asm volatile("ldmatrix.sync.aligned.m8n8.x4.shared.b16 {%0,%1,%2,%3}, [%4];"
        : "=r"(r[0]), "=r"(r[1]), "=r"(r[2]), "=r"(r[3]) : "r"(addr));
}
__device__ __forceinline__ void mma16816(float* d, const uint32_t* a, uint32_t b0, uint32_t b1) {
    asm volatile("mma.sync.aligned.m16n8k16.row.col.f32.f16.f16.f32 "
        "{%0,%1,%2,%3}, {%4,%5,%6,%7}, {%8,%9}, {%0,%1,%2,%3};"
        : "+f"(d[0]), "+f"(d[1]), "+f"(d[2]), "+f"(d[3])
        : "r"(a[0]), "r"(a[1]), "r"(a[2]), "r"(a[3]), "r"(b0), "r"(b1));
}
#define CP16(dst, src) \
    asm volatile("cp.async.cg.shared.global [%0], [%1], 16;" :: "r"(dst), "l"(src) : "memory")
#define CPCOMMIT() asm volatile("cp.async.commit_group;" ::: "memory")

// smem: per stage A(128x144B) + B(128x144B)
#define SROWB   144
#define HALF_T  (128 * SROWB)          // 18432
#define STAGE   (2 * HALF_T)           // 36864

// ---------------------------------------------------------------------------
// HMMA GEMM: CTA 128x128, 256 thr (8 warps 2m x 4n, warp 64x32), K-chunk 64,
// multi-stage cp.async pipeline, single-pass fp16.
// MODE 0: A = gather(x, shift+transpose) fp32->fp16 -> g_qkv     (K=128, N=384)
// MODE 1: A = g_attn; epi = unshift + LN1 + residual(x) -> x1h  (K=128, N=128)
// MODE 2: A = g_x1h;  epi = GELU -> g_h                          (K=128, N=512)
// MODE 3: A = g_h;    epi = LN2 + residual(x1h) -> out fp32      (K=512, N=128)
// ---------------------------------------------------------------------------
template<int MODE, int K>
__global__ __launch_bounds__(256, 2)
void tc_gemm(int woff, const float* __restrict__ bias, float* __restrict__ outp,
             const float* __restrict__ xin, const float* __restrict__ gamma,
             const float* __restrict__ beta)
{
    constexpr int NC = K / 64;
    constexpr int STAGES = (NC >= 3) ? 3 : 2;

    extern __shared__ __align__(1024) char smem[];
    const uint32_t sb = smem_u32(smem);
    const int tid = threadIdx.x;
    const int lane = tid & 31;
    const int wid = tid >> 5;
    const int wm = wid & 1;        // 2 m-blocks of 64
    const int wn = wid >> 1;       // 4 n-blocks of 32
    const int rowBlock = blockIdx.x * 128;
    const int colBlock = blockIdx.y * 128;

    // loader: 256 threads; chunk col (tid&7)*16B, rows (tid>>3) + 32j, j<4
    const int lcc  = tid & 7;
    const int lrow = tid >> 3;     // 0..31

    const float* g0row[4];
    const __half* asrc = nullptr;
    if (MODE == 0) {
        #pragma unroll
        for (int j = 0; j < 4; j++) {
            int gr = rowBlock + lrow + 32 * j;
            int b = gr / (NNH * LL), rem = gr % (NNH * LL);
            int n = rem / LL, ls = rem % LL;
            int l = ls - SHIFTSZ; if (l < 0) l += LL;
            g0row[j] = xin + ((size_t)(b * LL + l) * NNH + n) * DDIM;
        }
    } else if (MODE == 1) asrc = g_attn;
    else if (MODE == 2) asrc = g_x1h;
    else asrc = g_h;

    const __half* wsrc = g_w + woff;

    float acc[4][4][4];
    #pragma unroll
    for (int mt = 0; mt < 4; mt++)
        #pragma unroll
        for (int nt = 0; nt < 4; nt++)
            #pragma unroll
            for (int e = 0; e < 4; e++) acc[mt][nt][e] = 0.f;

    // ---- stage loader ----
    auto load_stage = [&](int ch, int s) {
        const int k0 = ch * 64 + lcc * 8;
        const uint32_t so = (uint32_t)lrow * SROWB + (uint32_t)lcc * 16;
        const uint32_t sA = sb + (uint32_t)s * STAGE;
        #pragma unroll
        for (int j = 0; j < 4; j++) {
            const uint32_t roff = so + (uint32_t)(j * 32 * SROWB);
            if (MODE == 0) {
                float4 f0 = *(const float4*)(g0row[j] + k0);
                float4 f1 = *(const float4*)(g0row[j] + k0 + 4);
                __align__(16) __half hv[8];
                hv[0] = __float2half_rn(f0.x); hv[1] = __float2half_rn(f0.y);
                hv[2] = __float2half_rn(f0.z); hv[3] = __float2half_rn(f0.w);
                hv[4] = __float2half_rn(f1.x); hv[5] = __float2half_rn(f1.y);
                hv[6] = __float2half_rn(f1.z); hv[7] = __float2half_rn(f1.w);
                *(uint4*)(smem + (size_t)s * STAGE + lrow * SROWB + lcc * 16 + j * 32 * SROWB) = *(uint4*)hv;
            } else {
                CP16(sA + roff, asrc + (size_t)(rowBlock + lrow + 32 * j) * K + k0);
            }
            CP16(sA + HALF_T + roff, wsrc + (size_t)(colBlock + lrow + 32 * j) * K + k0);
        }
        CPCOMMIT();
    };

    const int lmRow = lane & 15;
    const uint32_t lmColB = (uint32_t)((lane >> 4) * 16);

    // prologue
    load_stage(0, 0);
    if (STAGES >= 3 && NC >= 2) load_stage(1, 1);

    for (int ch = 0; ch < NC; ch++) {
        const int nxt = ch + STAGES - 1;
        if (nxt < NC) {
            load_stage(nxt, nxt % STAGES);
            if (STAGES == 3) asm volatile("cp.async.wait_group 2;" ::: "memory");
            else             asm volatile("cp.async.wait_group 1;" ::: "memory");
        } else {
            const int rem = NC - 1 - ch;  // groups that may stay in flight
            if (STAGES == 3 && rem >= 1) asm volatile("cp.async.wait_group 1;" ::: "memory");
            else                          asm volatile("cp.async.wait_group 0;" ::: "memory");
        }
        __syncthreads();

        const uint32_t sA = sb + (uint32_t)(ch % STAGES) * STAGE;
        const uint32_t sB = sA + HALF_T;
        #pragma unroll
        for (int kk = 0; kk < 4; kk++) {
            const uint32_t cb = (uint32_t)(kk * 32) + lmColB;
            uint32_t af[4][4], bf[2][4];
            #pragma unroll
            for (int mt = 0; mt < 4; mt++)
                ldm4(af[mt], sA + (uint32_t)(wm * 64 + mt * 16 + lmRow) * SROWB + cb);
            #pragma unroll
            for (int pt = 0; pt < 2; pt++)
                ldm4(bf[pt], sB + (uint32_t)(wn * 32 + pt * 16 + lmRow) * SROWB + cb);
            #pragma unroll
            for (int mt = 0; mt < 4; mt++)
                #pragma unroll
                for (int nt = 0; nt < 4; nt++)
                    mma16816(acc[mt][nt], af[mt], bf[nt >> 1][nt & 1], bf[nt >> 1][(nt & 1) + 2]);
        }
        __syncthreads();
    }

    // ---------------- epilogue ----------------
    if (MODE == 0 || MODE == 2) {
        const int ldst = (MODE == 0) ? 384 : 512;
        __half* base = (MODE == 0) ? g_qkv : g_h;
        #pragma unroll
        for (int mt = 0; mt < 4; mt++) {
            const int r0 = rowBlock + wm * 64 + mt * 16 + (lane >> 2);
            #pragma unroll
            for (int nt = 0; nt < 4; nt++) {
                const int c = colBlock + wn * 32 + nt * 8 + (lane & 3) * 2;
                const float b0 = bias[c], b1 = bias[c + 1];
                #pragma unroll
                for (int hh = 0; hh < 2; hh++) {
                    const int r = r0 + hh * 8;
                    float v0 = acc[mt][nt][hh * 2 + 0] + b0;
                    float v1 = acc[mt][nt][hh * 2 + 1] + b1;
                    if (MODE == 2) { v0 = v0 * normcdff(v0); v1 = v1 * normcdff(v1); }
                    *(__half2*)(base + (size_t)r * ldst + c) = __floats2half2_rn(v0, v1);
                }
            }
        }
        return;
    }

    // LN modes: stage acc(+bias) to smem fp32 [128][132], per-row LN
    float* sf = (float*)smem;  // pitch 132
    #pragma unroll
    for (int mt = 0; mt < 4; mt++) {
        const int r0 = wm * 64 + mt * 16 + (lane >> 2);
        #pragma unroll
        for (int nt = 0; nt < 4; nt++) {
            const int c = wn * 32 + nt * 8 + (lane & 3) * 2;
            const float b0 = bias[c], b1 = bias[c + 1];
            sf[(r0)     * 132 + c]     = acc[mt][nt][0] + b0;
            sf[(r0)     * 132 + c + 1] = acc[mt][nt][1] + b1;
            sf[(r0 + 8) * 132 + c]     = acc[mt][nt][2] + b0;
            sf[(r0 + 8) * 132 + c + 1] = acc[mt][nt][3] + b1;
        }
    }
    __syncthreads();

    if (tid < 128) {
        const int r = rowBlock + tid;
        const float* row = sf + tid * 132;
        float s = 0.f, s2 = 0.f;
        #pragma unroll 16
        for (int c = 0; c < 128; c++) { float v = row[c]; s += v; s2 += v * v; }
        const float mean = s * (1.f / 128.f);
        const float var = fmaxf(s2 * (1.f / 128.f) - mean * mean, 0.f);
        const float rstd = rsqrtf(var + 1e-5f);

        int b = r / (NNH * LL), rem = r % (NNH * LL);
        int n = rem / LL, li = rem % LL;

        if (MODE == 1) {
            int lo_ = li - SHIFTSZ; if (lo_ < 0) lo_ += LL;
            const float* resf = xin + ((size_t)(b * LL + lo_) * NNH + n) * DDIM;
            __half* dh = g_x1h + ((size_t)(b * NNH + n) * LL + lo_) * DDIM;
            for (int c = 0; c < 128; c += 2) {
                float y0 = (row[c]     - mean) * rstd * gamma[c]     + beta[c]     + resf[c];
                float y1 = (row[c + 1] - mean) * rstd * gamma[c + 1] + beta[c + 1] + resf[c + 1];
                *(__half2*)(dh + c) = __floats2half2_rn(y0, y1);
            }
        } else {
            const __half* resh = g_x1h + (size_t)r * 128;
            float* dst = outp + ((size_t)(b * LL + li) * NNH + n) * DDIM;
            for (int c = 0; c < 128; c += 4) {
                float4 o;
                o.x = (row[c]     - mean) * rstd * gamma[c]     + beta[c]     + __half2float(resh[c]);
                o.y = (row[c + 1] - mean) * rstd * gamma[c + 1] + beta[c + 1] + __half2float(resh[c + 1]);
                o.z = (row[c + 2] - mean) * rstd * gamma[c + 2] + beta[c + 2] + __half2float(resh[c + 2]);
                o.w = (row[c + 3] - mean) * rstd * gamma[c + 3] + beta[c + 3] + __half2float(resh[c + 3]);
                *(float4*)(dst + c) = o;
            }
        }
    }
}

// ---------------------------------------------------------------------------
// Weight prep: fp32 [K][N] -> transposed fp16 [N][K]
// ---------------------------------------------------------------------------
__global__ void prep_w(const float* __restrict__ qkv_w, const float* __restrict__ proj_w,
                       const float* __restrict__ fc1_w, const float* __restrict__ fc2_w)
{
    int idx = blockIdx.x * 256 + threadIdx.x;
    if (idx >= W_TOTAL) return;
    const float* src; int K, N, base;
    if (idx < OFF_PROJ)      { src = qkv_w;  K = 128; N = 384; base = OFF_QKV;  }
    else if (idx < OFF_FC1)  { src = proj_w; K = 128; N = 128; base = OFF_PROJ; }
    else if (idx < OFF_FC2)  { src = fc1_w;  K = 128; N = 512; base = OFF_FC1;  }
    else                     { src = fc2_w;  K = 512; N = 128; base = OFF_FC2;  }
    int local = idx - base;
    int nn = local / K, kk = local % K;
    g_w[idx] = __float2half_rn(src[(size_t)kk * N + nn]);
}

// ---------------------------------------------------------------------------
// Windowed attention: one block per (b, n, window). 96 threads = (head, row).
// ---------------------------------------------------------------------------
__global__ __launch_bounds__(96)
void attn_kernel()
{
    __shared__ float s[12 * 384];

    int blk = blockIdx.x;
    int w = blk % NWIN, rem = blk / NWIN;
    int n = rem % NNH, b = rem / NNH;
    size_t base = (size_t)(b * NNH + n) * LL + w * WSZ;

    int tid = threadIdx.x;
    for (int v = tid; v < 576; v += 96) {
        int i = v / 48, g = (v % 48) * 8;
        uint4 hv = *(const uint4*)(g_qkv + (base + i) * 384 + g);
        const __half* hb = (const __half*)&hv;
        #pragma unroll
        for (int e = 0; e < 8; e++) s[i * 384 + g + e] = __half2float(hb[e]);
    }
    __syncthreads();

    int h = tid / 12;
    int i = tid % 12;
    const float* q = &s[i * 384 + h * 16];
    bool gi = (i < SHIFTSZ);

    float sc[12];
    float mx = -1e30f;
    #pragma unroll
    for (int j = 0; j < 12; j++) {
        const float* kp = &s[j * 384 + 128 + h * 16];
        float a = 0.f;
        #pragma unroll
        for (int d = 0; d < 16; d++) a += q[d] * kp[d];
        a *= 0.25f;
        if (w == 0 && (gi != (j < SHIFTSZ))) a -= 100.f;
        sc[j] = a;
        mx = fmaxf(mx, a);
    }
    float den = 0.f;
    #pragma unroll
    for (int j = 0; j < 12; j++) { sc[j] = expf(sc[j] - mx); den += sc[j]; }
    float inv = 1.f / den;

    float o[16];
    #pragma unroll
    for (int d = 0; d < 16; d++) o[d] = 0.f;
    #pragma unroll
    for (int j = 0; j < 12; j++) {
        float p = sc[j] * inv;
        const float* vp = &s[j * 384 + 256 + h * 16];
        #pragma unroll
        for (int d = 0; d < 16; d++) o[d] += p * vp[d];
    }

    __align__(16) __half hv[16];
    #pragma unroll
    for (int d = 0; d < 16; d++) hv[d] = __float2half_rn(o[d]);
    __half* dst = g_attn + (base + i) * 128 + h * 16;
    *(uint4*)(dst)     = *(uint4*)(hv);
    *(uint4*)(dst + 8) = *(uint4*)(hv + 8);
}

// ---------------------------------------------------------------------------
extern "C" void kernel_launch(void* const* d_in, const int* in_sizes, int n_in,
                              void* d_out, int out_size)
{
    const float* x      = (const float*)d_in[0];
    const float* qkv_w  = (const float*)d_in[1];
    const float* qkv_b  = (const float*)d_in[2];
    const float* proj_w = (const float*)d_in[3];
    const float* proj_b = (const float*)d_in[4];
    const float* fc1_w  = (const float*)d_in[5];
    const float* fc1_b  = (const float*)d_in[6];
    const float* fc2_w  = (const float*)d_in[7];
    const float* fc2_b  = (const float*)d_in[8];
    const float* g1     = (const float*)d_in[9];
    const float* b1     = (const float*)d_in[10];
    const float* g2     = (const float*)d_in[11];
    const float* b2     = (const float*)d_in[12];
    float* out = (float*)d_out;

    static bool attr_done = false;
    if (!attr_done) {
        cudaFuncSetAttribute(tc_gemm<0, 128>, cudaFuncAttributeMaxDynamicSharedMemorySize, 2 * STAGE);
        cudaFuncSetAttribute(tc_gemm<1, 128>, cudaFuncAttributeMaxDynamicSharedMemorySize, 2 * STAGE);
        cudaFuncSetAttribute(tc_gemm<2, 128>, cudaFuncAttributeMaxDynamicSharedMemorySize, 2 * STAGE);
        cudaFuncSetAttribute(tc_gemm<3, 512>, cudaFuncAttributeMaxDynamicSharedMemorySize, 3 * STAGE);
        attr_done = true;
    }

    const int MB = MTOK / 128; // 1530

    // 0) weight transpose to fp16 [N][K]
    prep_w<<<(W_TOTAL + 255) / 256, 256>>>(qkv_w, proj_w, fc1_w, fc2_w);
    // 1) QKV projection (shift+transpose gather fused into A load)
    tc_gemm<0, 128><<<dim3(MB, 3), 256, 2 * STAGE>>>(OFF_QKV, qkv_b, nullptr, x, nullptr, nullptr);
    // 2) windowed attention
    attn_kernel<<<BB * NNH * NWIN, 96>>>();
    // 3) proj + unshift + LN1 + residual(x)
    tc_gemm<1, 128><<<dim3(MB, 1), 256, 2 * STAGE>>>(OFF_PROJ, proj_b, nullptr, x, g1, b1);
    // 4) fc1 + GELU
    tc_gemm<2, 128><<<dim3(MB, 4), 256, 2 * STAGE>>>(OFF_FC1, fc1_b, nullptr, nullptr, nullptr, nullptr);
    // 5) fc2 + LN2 + residual(x1h) + scatter to (B,L,N,D)
    tc_gemm<3, 512><<<dim3(MB, 1), 256, 3 * STAGE>>>(OFF_FC2, fc2_b, out, nullptr, g2, b2);
}

// round 7
// speedup vs baseline: 3.4842x; 1.2090x over previous
#include <cuda_runtime.h>
#include <cuda_fp16.h>
#include <math.h>
#include <stdint.h>

#define BB      4
#define LL      288
#define NNH     170
#define DDIM    128
#define WSZ     12
#define SHIFTSZ 6
#define HIDD    512
#define NWIN    24
#define MTOK    (BB * LL * NNH)   // 195840

// ---------------- scratch (fp16 activations) ----------------
__device__ __align__(256) __half g_xh[(size_t)MTOK * 128];    // shifted/transposed x, fp16
__device__ __align__(256) __half g_qkv[(size_t)MTOK * 384];
__device__ __align__(256) __half g_attn[(size_t)MTOK * 128];
__device__ __align__(256) __half g_x1h[(size_t)MTOK * 128];
__device__ __align__(256) __half g_h[(size_t)MTOK * 512];
// transposed weights [N][K], fp16
#define OFF_QKV  0
#define OFF_PROJ 49152
#define OFF_FC1  65536
#define OFF_FC2  131072
#define W_TOTAL  196608
__device__ __align__(256) __half g_w[W_TOTAL];

// ---------------- helpers ----------------
__device__ __forceinline__ uint32_t smem_u32(const void* p) {
    uint32_t a;
    asm("{ .reg .u64 t; cvta.to.shared.u64 t, %1; cvt.u32.u64 %0, t; }" : "=r"(a) : "l"(p));
    return a;
}
__device__ __forceinline__ void ldm4(uint32_t* r, uint32_t addr) {
    asm volatile("ldmatrix.sync.aligned.m8n8.x4.shared.b16 {%0,%1,%2,%3}, [%4];"
        : "=r"(r[0]), "=r"(r[1]), "=r"(r[2]), "=r"(r[3]) : "r"(addr));
}
__device__ __forceinline__ void mma16816(float* d, const uint32_t* a, uint32_t b0, uint32_t b1) {
    asm volatile("mma.sync.aligned.m16n8k16.row.col.f32.f16.f16.f32 "
        "{%0,%1,%2,%3}, {%4,%5,%6,%7}, {%8,%9}, {%0,%1,%2,%3};"
        : "+f"(d[0]), "+f"(d[1]), "+f"(d[2]), "+f"(d[3])
        : "r"(a[0]), "r"(a[1]), "r"(a[2]), "r"(a[3]), "r"(b0), "r"(b1));
}
#define CP16(dst, src) \
    asm volatile("cp.async.cg.shared.global [%0], [%1], 16;" :: "r"(dst), "l"(src) : "memory")
#define CPCOMMIT() asm volatile("cp.async.commit_group;" ::: "memory")

// stage: A 64x128B (swizzled) + B 128x128B (swizzled)
#define A_T     8192
#define B_T     16384
#define STAGE   (A_T + B_T)            // 24576
#define EPI_B   32768                  // 64 x 128 fp32 (permuted)

// ---------------------------------------------------------------------------
// HMMA GEMM: CTA 64x128, 256 thr (8 warps 2m x 4n, warp 32x32), K-chunk 64,
// cp.async pipeline + XOR-swizzled smem, warp-per-row coalesced epilogue.
// MODE 0: A = g_xh;   epi = +bias -> g_qkv                      (K=128, N=384)
// MODE 1: A = g_attn; epi = unshift + LN1 + residual(x) -> x1h  (K=128, N=128)
// MODE 2: A = g_x1h;  epi = GELU -> g_h                          (K=128, N=512)
// MODE 3: A = g_h;    epi = LN2 + residual(x1h) -> out fp32      (K=512, N=128)
// ---------------------------------------------------------------------------
template<int MODE, int K>
__global__ __launch_bounds__(256, 3)
void tc_gemm(int woff, const float* __restrict__ bias, float* __restrict__ outp,
             const float* __restrict__ xin, const float* __restrict__ gamma,
             const float* __restrict__ beta)
{
    constexpr int NC = K / 64;
    constexpr int STAGES = (NC >= 3) ? 3 : 2;

    extern __shared__ __align__(1024) char smem[];
    const uint32_t sb = smem_u32(smem);
    const int tid = threadIdx.x;
    const int lane = tid & 31;
    const int wid = tid >> 5;
    const int wm = wid & 1;        // 2 m-blocks of 32
    const int wn = wid >> 1;       // 4 n-blocks of 32
    const int rowBlock = blockIdx.x * 64;
    const int colBlock = blockIdx.y * 128;

    const __half* asrc;
    if (MODE == 0) asrc = g_xh;
    else if (MODE == 1) asrc = g_attn;
    else if (MODE == 2) asrc = g_x1h;
    else asrc = g_h;
    const __half* wsrc = g_w + woff;

    // loader: chunk col (tid&7), rows (tid>>3)+32j
    const int lcc  = tid & 7;
    const int lrow = tid >> 3;                 // 0..31
    const uint32_t swo = (uint32_t)(lcc ^ (lrow & 7)) * 16;

    float acc[2][4][4];
    #pragma unroll
    for (int mt = 0; mt < 2; mt++)
        #pragma unroll
        for (int nt = 0; nt < 4; nt++)
            #pragma unroll
            for (int e = 0; e < 4; e++) acc[mt][nt][e] = 0.f;

    auto load_stage = [&](int ch, int s) {
        const int k0 = ch * 64 + lcc * 8;
        const uint32_t sA = sb + (uint32_t)s * STAGE;
        #pragma unroll
        for (int j = 0; j < 2; j++) {
            const int row = lrow + 32 * j;
            CP16(sA + (uint32_t)row * 128 + swo, asrc + (size_t)(rowBlock + row) * K + k0);
        }
        #pragma unroll
        for (int j = 0; j < 4; j++) {
            const int row = lrow + 32 * j;
            CP16(sA + A_T + (uint32_t)row * 128 + swo, wsrc + (size_t)(colBlock + row) * K + k0);
        }
        CPCOMMIT();
    };

    const int lmRow = lane & 15;
    const int lmHalf = lane >> 4;

    load_stage(0, 0);
    if (STAGES >= 3 && NC >= 2) load_stage(1, 1);

    for (int ch = 0; ch < NC; ch++) {
        const int nxt = ch + STAGES - 1;
        if (nxt < NC) {
            load_stage(nxt, nxt % STAGES);
            if (STAGES == 3) asm volatile("cp.async.wait_group 2;" ::: "memory");
            else             asm volatile("cp.async.wait_group 1;" ::: "memory");
        } else {
            if (STAGES == 3 && ch < NC - 1) asm volatile("cp.async.wait_group 1;" ::: "memory");
            else                             asm volatile("cp.async.wait_group 0;" ::: "memory");
        }
        __syncthreads();

        const uint32_t sA = sb + (uint32_t)(ch % STAGES) * STAGE;
        const uint32_t sB = sA + A_T;
        #pragma unroll
        for (int kk = 0; kk < 4; kk++) {
            const int chk = kk * 2 + lmHalf;
            uint32_t af[2][4], bf[2][4];
            #pragma unroll
            for (int mt = 0; mt < 2; mt++) {
                const int rA = wm * 32 + mt * 16 + lmRow;
                ldm4(af[mt], sA + (uint32_t)rA * 128 + (uint32_t)((chk ^ (rA & 7)) * 16));
            }
            #pragma unroll
            for (int pt = 0; pt < 2; pt++) {
                const int rB = wn * 32 + pt * 16 + lmRow;
                ldm4(bf[pt], sB + (uint32_t)rB * 128 + (uint32_t)((chk ^ (rB & 7)) * 16));
            }
            #pragma unroll
            for (int mt = 0; mt < 2; mt++)
                #pragma unroll
                for (int nt = 0; nt < 4; nt++)
                    mma16816(acc[mt][nt], af[mt], bf[nt >> 1][nt & 1], bf[nt >> 1][(nt & 1) + 2]);
        }
        __syncthreads();
    }

    // ---------------- stage acc into permuted fp32 buffer [64][128] ----------------
    float* sf = (float*)smem;
    #pragma unroll
    for (int mt = 0; mt < 2; mt++) {
        #pragma unroll
        for (int nt = 0; nt < 4; nt++) {
            const int r0 = wm * 32 + mt * 16 + (lane >> 2);
            const int c  = wn * 32 + nt * 8 + (lane & 3) * 2;
            const int p0 = (c + 8 * r0) & 127;
            *(float2*)(sf + r0 * 128 + p0) = make_float2(acc[mt][nt][0], acc[mt][nt][1]);
            const int r1 = r0 + 8;
            const int p1 = (c + 8 * r1) & 127;
            *(float2*)(sf + r1 * 128 + p1) = make_float2(acc[mt][nt][2], acc[mt][nt][3]);
        }
    }
    __syncthreads();

    // ---------------- warp-per-row coalesced epilogue ----------------
    #pragma unroll 1
    for (int rr = 0; rr < 8; rr++) {
        const int lr = wid * 8 + rr;
        const int r  = rowBlock + lr;
        float4 v = *(float4*)(sf + lr * 128 + lane * 4);
        const int col = (lane * 4 - lr * 8) & 127;           // logical column (mult of 4)
        const float4 bv = *(const float4*)(bias + ((MODE == 0 || MODE == 2) ? colBlock : 0) + col);
        v.x += bv.x; v.y += bv.y; v.z += bv.z; v.w += bv.w;

        if (MODE == 0 || MODE == 2) {
            if (MODE == 2) {
                v.x *= normcdff(v.x); v.y *= normcdff(v.y);
                v.z *= normcdff(v.z); v.w *= normcdff(v.w);
            }
            __align__(8) __half hv[4];
            hv[0] = __float2half_rn(v.x); hv[1] = __float2half_rn(v.y);
            hv[2] = __float2half_rn(v.z); hv[3] = __float2half_rn(v.w);
            const int ld = (MODE == 0) ? 384 : 512;
            __half* base = (MODE == 0) ? g_qkv : g_h;
            *(uint2*)(base + (size_t)r * ld + colBlock + col) = *(uint2*)hv;
        } else {
            // LayerNorm over the 128-wide row
            float s  = v.x + v.y + v.z + v.w;
            float s2 = v.x * v.x + v.y * v.y + v.z * v.z + v.w * v.w;
            #pragma unroll
            for (int off = 16; off > 0; off >>= 1) {
                s  += __shfl_xor_sync(0xFFFFFFFFu, s,  off);
                s2 += __shfl_xor_sync(0xFFFFFFFFu, s2, off);
            }
            const float mean = s * (1.f / 128.f);
            const float var  = fmaxf(s2 * (1.f / 128.f) - mean * mean, 0.f);
            const float rstd = rsqrtf(var + 1e-5f);

            const float4 gv = *(const float4*)(gamma + col);
            const float4 be = *(const float4*)(beta + col);

            int b = r / (NNH * LL), rem = r % (NNH * LL);
            int n = rem / LL, li = rem % LL;

            if (MODE == 1) {
                int lo_ = li - SHIFTSZ; if (lo_ < 0) lo_ += LL;
                const float4 res = *(const float4*)(xin + ((size_t)(b * LL + lo_) * NNH + n) * DDIM + col);
                float y0 = (v.x - mean) * rstd * gv.x + be.x + res.x;
                float y1 = (v.y - mean) * rstd * gv.y + be.y + res.y;
                float y2 = (v.z - mean) * rstd * gv.z + be.z + res.z;
                float y3 = (v.w - mean) * rstd * gv.w + be.w + res.w;
                __align__(8) __half hv[4];
                hv[0] = __float2half_rn(y0); hv[1] = __float2half_rn(y1);
                hv[2] = __float2half_rn(y2); hv[3] = __float2half_rn(y3);
                __half* dh = g_x1h + ((size_t)(b * NNH + n) * LL + lo_) * DDIM + col;
                *(uint2*)dh = *(uint2*)hv;
            } else {
                const uint2 rh = *(const uint2*)(g_x1h + (size_t)r * 128 + col);
                const __half* rp = (const __half*)&rh;
                float4 o;
                o.x = (v.x - mean) * rstd * gv.x + be.x + __half2float(rp[0]);
                o.y = (v.y - mean) * rstd * gv.y + be.y + __half2float(rp[1]);
                o.z = (v.z - mean) * rstd * gv.z + be.z + __half2float(rp[2]);
                o.w = (v.w - mean) * rstd * gv.w + be.w + __half2float(rp[3]);
                *(float4*)(outp + ((size_t)(b * LL + li) * NNH + n) * DDIM + col) = o;
            }
        }
    }
}

// ---------------------------------------------------------------------------
// prep_x: x (B,L,N,D fp32) -> g_xh (b,n,ls) fp16 with shift fused. Warp per row.
// ---------------------------------------------------------------------------
__global__ __launch_bounds__(256)
void prep_x(const float* __restrict__ x)
{
    const int row = blockIdx.x * 8 + (threadIdx.x >> 5);
    const int lane = threadIdx.x & 31;
    int b = row / (NNH * LL), rem = row % (NNH * LL);
    int n = rem / LL, ls = rem % LL;
    int l = ls - SHIFTSZ; if (l < 0) l += LL;
    const float4 v = *(const float4*)(x + ((size_t)(b * LL + l) * NNH + n) * DDIM + lane * 4);
    __align__(8) __half hv[4];
    hv[0] = __float2half_rn(v.x); hv[1] = __float2half_rn(v.y);
    hv[2] = __float2half_rn(v.z); hv[3] = __float2half_rn(v.w);
    *(uint2*)(g_xh + (size_t)row * 128 + lane * 4) = *(uint2*)hv;
}

// ---------------------------------------------------------------------------
// Weight prep: fp32 [K][N] -> transposed fp16 [N][K]
// ---------------------------------------------------------------------------
__global__ void prep_w(const float* __restrict__ qkv_w, const float* __restrict__ proj_w,
                       const float* __restrict__ fc1_w, const float* __restrict__ fc2_w)
{
    int idx = blockIdx.x * 256 + threadIdx.x;
    if (idx >= W_TOTAL) return;
    const float* src; int K, N, base;
    if (idx < OFF_PROJ)      { src = qkv_w;  K = 128; N = 384; base = OFF_QKV;  }
    else if (idx < OFF_FC1)  { src = proj_w; K = 128; N = 128; base = OFF_PROJ; }
    else if (idx < OFF_FC2)  { src = fc1_w;  K = 128; N = 512; base = OFF_FC1;  }
    else                     { src = fc2_w;  K = 512; N = 128; base = OFF_FC2;  }
    int local = idx - base;
    int nn = local / K, kk = local % K;
    g_w[idx] = __float2half_rn(src[(size_t)kk * N + nn]);
}

// ---------------------------------------------------------------------------
// Windowed attention: one block per (b, n, window). 96 threads = (head, row).
// ---------------------------------------------------------------------------
__global__ __launch_bounds__(96)
void attn_kernel()
{
    __shared__ float s[12 * 384];

    int blk = blockIdx.x;
    int w = blk % NWIN, rem = blk / NWIN;
    int n = rem % NNH, b = rem / NNH;
    size_t base = (size_t)(b * NNH + n) * LL + w * WSZ;

    int tid = threadIdx.x;
    for (int v = tid; v < 576; v += 96) {
        int i = v / 48, g = (v % 48) * 8;
        uint4 hv = *(const uint4*)(g_qkv + (base + i) * 384 + g);
        const __half* hb = (const __half*)&hv;
        #pragma unroll
        for (int e = 0; e < 8; e++) s[i * 384 + g + e] = __half2float(hb[e]);
    }
    __syncthreads();

    int h = tid / 12;
    int i = tid % 12;
    const float* q = &s[i * 384 + h * 16];
    bool gi = (i < SHIFTSZ);

    float sc[12];
    float mx = -1e30f;
    #pragma unroll
    for (int j = 0; j < 12; j++) {
        const float* kp = &s[j * 384 + 128 + h * 16];
        float a = 0.f;
        #pragma unroll
        for (int d = 0; d < 16; d++) a += q[d] * kp[d];
        a *= 0.25f;
        if (w == 0 && (gi != (j < SHIFTSZ))) a -= 100.f;
        sc[j] = a;
        mx = fmaxf(mx, a);
    }
    float den = 0.f;
    #pragma unroll
    for (int j = 0; j < 12; j++) { sc[j] = expf(sc[j] - mx); den += sc[j]; }
    float inv = 1.f / den;

    float o[16];
    #pragma unroll
    for (int d = 0; d < 16; d++) o[d] = 0.f;
    #pragma unroll
    for (int j = 0; j < 12; j++) {
        float p = sc[j] * inv;
        const float* vp = &s[j * 384 + 256 + h * 16];
        #pragma unroll
        for (int d = 0; d < 16; d++) o[d] += p * vp[d];
    }

    __align__(16) __half hv[16];
    #pragma unroll
    for (int d = 0; d < 16; d++) hv[d] = __float2half_rn(o[d]);
    __half* dst = g_attn + (base + i) * 128 + h * 16;
    *(uint4*)(dst)     = *(uint4*)(hv);
    *(uint4*)(dst + 8) = *(uint4*)(hv + 8);
}

// ---------------------------------------------------------------------------
extern "C" void kernel_launch(void* const* d_in, const int* in_sizes, int n_in,
                              void* d_out, int out_size)
{
    const float* x      = (const float*)d_in[0];
    const float* qkv_w  = (const float*)d_in[1];
    const float* qkv_b  = (const float*)d_in[2];
    const float* proj_w = (const float*)d_in[3];
    const float* proj_b = (const float*)d_in[4];
    const float* fc1_w  = (const float*)d_in[5];
    const float* fc1_b  = (const float*)d_in[6];
    const float* fc2_w  = (const float*)d_in[7];
    const float* fc2_b  = (const float*)d_in[8];
    const float* g1     = (const float*)d_in[9];
    const float* b1     = (const float*)d_in[10];
    const float* g2     = (const float*)d_in[11];
    const float* b2     = (const float*)d_in[12];
    float* out = (float*)d_out;

    const int SM128 = 2 * STAGE > EPI_B ? 2 * STAGE : EPI_B;   // 49152
    const int SM512 = 3 * STAGE;                                // 73728

    static bool attr_done = false;
    if (!attr_done) {
        cudaFuncSetAttribute(tc_gemm<0, 128>, cudaFuncAttributeMaxDynamicSharedMemorySize, SM128);
        cudaFuncSetAttribute(tc_gemm<1, 128>, cudaFuncAttributeMaxDynamicSharedMemorySize, SM128);
        cudaFuncSetAttribute(tc_gemm<2, 128>, cudaFuncAttributeMaxDynamicSharedMemorySize, SM128);
        cudaFuncSetAttribute(tc_gemm<3, 512>, cudaFuncAttributeMaxDynamicSharedMemorySize, SM512);
        attr_done = true;
    }

    const int MB = MTOK / 64; // 3060

    // 0) weight transpose to fp16 [N][K]; x gather/shift to fp16
    prep_w<<<(W_TOTAL + 255) / 256, 256>>>(qkv_w, proj_w, fc1_w, fc2_w);
    prep_x<<<MTOK / 8, 256>>>(x);
    // 1) QKV projection
    tc_gemm<0, 128><<<dim3(MB, 3), 256, SM128>>>(OFF_QKV, qkv_b, nullptr, x, nullptr, nullptr);
    // 2) windowed attention
    attn_kernel<<<BB * NNH * NWIN, 96>>>();
    // 3) proj + unshift + LN1 + residual(x)
    tc_gemm<1, 128><<<dim3(MB, 1), 256, SM128>>>(OFF_PROJ, proj_b, nullptr, x, g1, b1);
    // 4) fc1 + GELU
    tc_gemm<2, 128><<<dim3(MB, 4), 256, SM128>>>(OFF_FC1, fc1_b, nullptr, nullptr, nullptr, nullptr);
    // 5) fc2 + LN2 + residual(x1h) + scatter to (B,L,N,D)
    tc_gemm<3, 512><<<dim3(MB, 1), 256, SM512>>>(OFF_FC2, fc2_b, out, nullptr, g2, b2);
}

// round 8
// speedup vs baseline: 3.7416x; 1.0738x over previous
#include <cuda_runtime.h>
#include <cuda_fp16.h>
#include <math.h>
#include <stdint.h>

#define BB      4
#define LL      288
#define NNH     170
#define DDIM    128
#define WSZ     12
#define SHIFTSZ 6
#define HIDD    512
#define NWIN    24
#define MTOK    (BB * LL * NNH)   // 195840

// ---------------- scratch (fp16 activations) ----------------
__device__ __align__(256) __half g_xh[(size_t)MTOK * 128];    // shifted/transposed x, fp16
__device__ __align__(256) __half g_qkv[(size_t)MTOK * 384];
__device__ __align__(256) __half g_attn[(size_t)MTOK * 128];
__device__ __align__(256) __half g_x1h[(size_t)MTOK * 128];
__device__ __align__(256) __half g_h[(size_t)MTOK * 512];
// transposed weights [N][K], fp16
#define OFF_QKV  0
#define OFF_PROJ 49152
#define OFF_FC1  65536
#define OFF_FC2  131072
#define W_TOTAL  196608
__device__ __align__(256) __half g_w[W_TOTAL];

// ---------------- helpers ----------------
__device__ __forceinline__ uint32_t smem_u32(const void* p) {
    uint32_t a;
    asm("{ .reg .u64 t; cvta.to.shared.u64 t, %1; cvt.u32.u64 %0, t; }" : "=r"(a) : "l"(p));
    return a;
}
__device__ __forceinline__ void ldm4(uint32_t* r, uint32_t addr) {
    asm volatile("ldmatrix.sync.aligned.m8n8.x4.shared.b16 {%0,%1,%2,%3}, [%4];"
        : "=r"(r[0]), "=r"(r[1]), "=r"(r[2]), "=r"(r[3]) : "r"(addr));
}
__device__ __forceinline__ void mma16816(float* d, const uint32_t* a, uint32_t b0, uint32_t b1) {
    asm volatile("mma.sync.aligned.m16n8k16.row.col.f32.f16.f16.f32 "
        "{%0,%1,%2,%3}, {%4,%5,%6,%7}, {%8,%9}, {%0,%1,%2,%3};"
        : "+f"(d[0]), "+f"(d[1]), "+f"(d[2]), "+f"(d[3])
        : "r"(a[0]), "r"(a[1]), "r"(a[2]), "r"(a[3]), "r"(b0), "r"(b1));
}
#define CP16(dst, src) \
    asm volatile("cp.async.cg.shared.global [%0], [%1], 16;" :: "r"(dst), "l"(src) : "memory")
#define CPCOMMIT() asm volatile("cp.async.commit_group;" ::: "memory")

// stage: A 64x128B (swizzled) + B 128x128B (swizzled)
#define A_T     8192
#define B_T     16384
#define STAGE   (A_T + B_T)            // 24576
#define EPI_B   32768                  // 64 x 128 fp32 (permuted)

// ---------------------------------------------------------------------------
// HMMA GEMM: CTA 64x128, 256 thr (8 warps 2m x 4n, warp 32x32), K-chunk 64,
// cp.async pipeline + XOR-swizzled smem, warp-per-row coalesced epilogue.
// MODE 0: A = g_xh;   epi = +bias -> g_qkv                      (K=128, N=384)
// MODE 1: A = g_attn; epi = unshift + LN1 + residual(x) -> x1h  (K=128, N=128)
// MODE 2: A = g_x1h;  epi = GELU -> g_h                          (K=128, N=512)
// MODE 3: A = g_h;    epi = LN2 + residual(x1h) -> out fp32      (K=512, N=128)
// ---------------------------------------------------------------------------
template<int MODE, int K>
__global__ __launch_bounds__(256, 3)
void tc_gemm(int woff, const float* __restrict__ bias, float* __restrict__ outp,
             const float* __restrict__ xin, const float* __restrict__ gamma,
             const float* __restrict__ beta)
{
    constexpr int NC = K / 64;
    constexpr int STAGES = (NC >= 3) ? 3 : 2;

    extern __shared__ __align__(1024) char smem[];
    const uint32_t sb = smem_u32(smem);
    const int tid = threadIdx.x;
    const int lane = tid & 31;
    const int wid = tid >> 5;
    const int wm = wid & 1;        // 2 m-blocks of 32
    const int wn = wid >> 1;       // 4 n-blocks of 32
    const int rowBlock = blockIdx.x * 64;
    const int colBlock = blockIdx.y * 128;

    const __half* asrc;
    if (MODE == 0) asrc = g_xh;
    else if (MODE == 1) asrc = g_attn;
    else if (MODE == 2) asrc = g_x1h;
    else asrc = g_h;
    const __half* wsrc = g_w + woff;

    // loader: chunk col (tid&7), rows (tid>>3)+32j
    const int lcc  = tid & 7;
    const int lrow = tid >> 3;                 // 0..31
    const uint32_t swo = (uint32_t)(lcc ^ (lrow & 7)) * 16;

    float acc[2][4][4];
    #pragma unroll
    for (int mt = 0; mt < 2; mt++)
        #pragma unroll
        for (int nt = 0; nt < 4; nt++)
            #pragma unroll
            for (int e = 0; e < 4; e++) acc[mt][nt][e] = 0.f;

    auto load_stage = [&](int ch, int s) {
        const int k0 = ch * 64 + lcc * 8;
        const uint32_t sA = sb + (uint32_t)s * STAGE;
        #pragma unroll
        for (int j = 0; j < 2; j++) {
            const int row = lrow + 32 * j;
            CP16(sA + (uint32_t)row * 128 + swo, asrc + (size_t)(rowBlock + row) * K + k0);
        }
        #pragma unroll
        for (int j = 0; j < 4; j++) {
            const int row = lrow + 32 * j;
            CP16(sA + A_T + (uint32_t)row * 128 + swo, wsrc + (size_t)(colBlock + row) * K + k0);
        }
        CPCOMMIT();
    };

    const int lmRow = lane & 15;
    const int lmHalf = lane >> 4;

    load_stage(0, 0);
    if (STAGES >= 3 && NC >= 2) load_stage(1, 1);

    for (int ch = 0; ch < NC; ch++) {
        const int nxt = ch + STAGES - 1;
        if (nxt < NC) {
            load_stage(nxt, nxt % STAGES);
            if (STAGES == 3) asm volatile("cp.async.wait_group 2;" ::: "memory");
            else             asm volatile("cp.async.wait_group 1;" ::: "memory");
        } else {
            if (STAGES == 3 && ch < NC - 1) asm volatile("cp.async.wait_group 1;" ::: "memory");
            else                             asm volatile("cp.async.wait_group 0;" ::: "memory");
        }
        __syncthreads();

        const uint32_t sA = sb + (uint32_t)(ch % STAGES) * STAGE;
        const uint32_t sB = sA + A_T;
        #pragma unroll
        for (int kk = 0; kk < 4; kk++) {
            const int chk = kk * 2 + lmHalf;
            uint32_t af[2][4], bf[2][4];
            #pragma unroll
            for (int mt = 0; mt < 2; mt++) {
                const int rA = wm * 32 + mt * 16 + lmRow;
                ldm4(af[mt], sA + (uint32_t)rA * 128 + (uint32_t)((chk ^ (rA & 7)) * 16));
            }
            #pragma unroll
            for (int pt = 0; pt < 2; pt++) {
                const int rB = wn * 32 + pt * 16 + lmRow;
                ldm4(bf[pt], sB + (uint32_t)rB * 128 + (uint32_t)((chk ^ (rB & 7)) * 16));
            }
            #pragma unroll
            for (int mt = 0; mt < 2; mt++)
                #pragma unroll
                for (int nt = 0; nt < 4; nt++)
                    mma16816(acc[mt][nt], af[mt], bf[nt >> 1][nt & 1], bf[nt >> 1][(nt & 1) + 2]);
        }
        __syncthreads();
    }

    // ---------------- stage acc into permuted fp32 buffer [64][128] ----------------
    float* sf = (float*)smem;
    #pragma unroll
    for (int mt = 0; mt < 2; mt++) {
        #pragma unroll
        for (int nt = 0; nt < 4; nt++) {
            const int r0 = wm * 32 + mt * 16 + (lane >> 2);
            const int c  = wn * 32 + nt * 8 + (lane & 3) * 2;
            const int p0 = (c + 8 * r0) & 127;
            *(float2*)(sf + r0 * 128 + p0) = make_float2(acc[mt][nt][0], acc[mt][nt][1]);
            const int r1 = r0 + 8;
            const int p1 = (c + 8 * r1) & 127;
            *(float2*)(sf + r1 * 128 + p1) = make_float2(acc[mt][nt][2], acc[mt][nt][3]);
        }
    }
    __syncthreads();

    // ---------------- warp-per-row coalesced epilogue ----------------
    #pragma unroll 1
    for (int rr = 0; rr < 8; rr++) {
        const int lr = wid * 8 + rr;
        const int r  = rowBlock + lr;
        float4 v = *(float4*)(sf + lr * 128 + lane * 4);
        const int col = (lane * 4 - lr * 8) & 127;           // logical column (mult of 4)
        const float4 bv = *(const float4*)(bias + ((MODE == 0 || MODE == 2) ? colBlock : 0) + col);
        v.x += bv.x; v.y += bv.y; v.z += bv.z; v.w += bv.w;

        if (MODE == 0 || MODE == 2) {
            if (MODE == 2) {
                v.x *= normcdff(v.x); v.y *= normcdff(v.y);
                v.z *= normcdff(v.z); v.w *= normcdff(v.w);
            }
            __align__(8) __half hv[4];
            hv[0] = __float2half_rn(v.x); hv[1] = __float2half_rn(v.y);
            hv[2] = __float2half_rn(v.z); hv[3] = __float2half_rn(v.w);
            const int ld = (MODE == 0) ? 384 : 512;
            __half* base = (MODE == 0) ? g_qkv : g_h;
            *(uint2*)(base + (size_t)r * ld + colBlock + col) = *(uint2*)hv;
        } else {
            // LayerNorm over the 128-wide row
            float s  = v.x + v.y + v.z + v.w;
            float s2 = v.x * v.x + v.y * v.y + v.z * v.z + v.w * v.w;
            #pragma unroll
            for (int off = 16; off > 0; off >>= 1) {
                s  += __shfl_xor_sync(0xFFFFFFFFu, s,  off);
                s2 += __shfl_xor_sync(0xFFFFFFFFu, s2, off);
            }
            const float mean = s * (1.f / 128.f);
            const float var  = fmaxf(s2 * (1.f / 128.f) - mean * mean, 0.f);
            const float rstd = rsqrtf(var + 1e-5f);

            const float4 gv = *(const float4*)(gamma + col);
            const float4 be = *(const float4*)(beta + col);

            int b = r / (NNH * LL), rem = r % (NNH * LL);
            int n = rem / LL, li = rem % LL;

            if (MODE == 1) {
                int lo_ = li - SHIFTSZ; if (lo_ < 0) lo_ += LL;
                const float4 res = *(const float4*)(xin + ((size_t)(b * LL + lo_) * NNH + n) * DDIM + col);
                float y0 = (v.x - mean) * rstd * gv.x + be.x + res.x;
                float y1 = (v.y - mean) * rstd * gv.y + be.y + res.y;
                float y2 = (v.z - mean) * rstd * gv.z + be.z + res.z;
                float y3 = (v.w - mean) * rstd * gv.w + be.w + res.w;
                __align__(8) __half hv[4];
                hv[0] = __float2half_rn(y0); hv[1] = __float2half_rn(y1);
                hv[2] = __float2half_rn(y2); hv[3] = __float2half_rn(y3);
                __half* dh = g_x1h + ((size_t)(b * NNH + n) * LL + lo_) * DDIM + col;
                *(uint2*)dh = *(uint2*)hv;
            } else {
                const uint2 rh = *(const uint2*)(g_x1h + (size_t)r * 128 + col);
                const __half* rp = (const __half*)&rh;
                float4 o;
                o.x = (v.x - mean) * rstd * gv.x + be.x + __half2float(rp[0]);
                o.y = (v.y - mean) * rstd * gv.y + be.y + __half2float(rp[1]);
                o.z = (v.z - mean) * rstd * gv.z + be.z + __half2float(rp[2]);
                o.w = (v.w - mean) * rstd * gv.w + be.w + __half2float(rp[3]);
                *(float4*)(outp + ((size_t)(b * LL + li) * NNH + n) * DDIM + col) = o;
            }
        }
    }
}

// ---------------------------------------------------------------------------
// prep_x: x (B,L,N,D fp32) -> g_xh (b,n,ls) fp16 with shift fused. Warp per row.
// ---------------------------------------------------------------------------
__global__ __launch_bounds__(256)
void prep_x(const float* __restrict__ x)
{
    const int row = blockIdx.x * 8 + (threadIdx.x >> 5);
    const int lane = threadIdx.x & 31;
    int b = row / (NNH * LL), rem = row % (NNH * LL);
    int n = rem / LL, ls = rem % LL;
    int l = ls - SHIFTSZ; if (l < 0) l += LL;
    const float4 v = *(const float4*)(x + ((size_t)(b * LL + l) * NNH + n) * DDIM + lane * 4);
    __align__(8) __half hv[4];
    hv[0] = __float2half_rn(v.x); hv[1] = __float2half_rn(v.y);
    hv[2] = __float2half_rn(v.z); hv[3] = __float2half_rn(v.w);
    *(uint2*)(g_xh + (size_t)row * 128 + lane * 4) = *(uint2*)hv;
}

// ---------------------------------------------------------------------------
// Weight prep: fp32 [K][N] -> transposed fp16 [N][K]
// ---------------------------------------------------------------------------
__global__ void prep_w(const float* __restrict__ qkv_w, const float* __restrict__ proj_w,
                       const float* __restrict__ fc1_w, const float* __restrict__ fc2_w)
{
    int idx = blockIdx.x * 256 + threadIdx.x;
    if (idx >= W_TOTAL) return;
    const float* src; int K, N, base;
    if (idx < OFF_PROJ)      { src = qkv_w;  K = 128; N = 384; base = OFF_QKV;  }
    else if (idx < OFF_FC1)  { src = proj_w; K = 128; N = 128; base = OFF_PROJ; }
    else if (idx < OFF_FC2)  { src = fc1_w;  K = 128; N = 512; base = OFF_FC1;  }
    else                     { src = fc2_w;  K = 512; N = 128; base = OFF_FC2;  }
    int local = idx - base;
    int nn = local / K, kk = local % K;
    g_w[idx] = __float2half_rn(src[(size_t)kk * N + nn]);
}

// ---------------------------------------------------------------------------
// Windowed attention: 192 threads = 2 windows x (head, row). qkv kept as raw
// __half in smem; all smem traffic is uint4 (LDS.128/STS.128).
// ---------------------------------------------------------------------------
__global__ __launch_bounds__(192)
void attn_kernel()
{
    __shared__ __half s[2][12 * 384];

    const int blk = blockIdx.x;            // over (b, n, window-pair)
    const int wp  = blk % (NWIN / 2);
    const int rem = blk / (NWIN / 2);
    const int n   = rem % NNH;
    const int b   = rem / NNH;
    const int half_id = threadIdx.x / 96;  // which window of the pair
    const int tid = threadIdx.x % 96;
    const int w   = wp * 2 + half_id;
    const size_t base = (size_t)(b * NNH + n) * LL + w * WSZ;

    // stage qkv (12 rows x 384 halves = 576 uint4) as raw halves
    __half* sp = s[half_id];
    const uint4* src = (const uint4*)(g_qkv + base * 384);
    uint4* dst = (uint4*)sp;
    #pragma unroll
    for (int v = 0; v < 6; v++)
        dst[tid + v * 96] = src[tid + v * 96];
    __syncthreads();

    const int h = tid / 12;
    const int i = tid % 12;
    const bool gi = (i < SHIFTSZ);

    // q -> registers (fp32)
    float q[16];
    {
        uint4 qa = *(const uint4*)(sp + i * 384 + h * 16);
        uint4 qb = *(const uint4*)(sp + i * 384 + h * 16 + 8);
        const __half2* pa = (const __half2*)&qa;
        const __half2* pb = (const __half2*)&qb;
        #pragma unroll
        for (int e = 0; e < 4; e++) {
            float2 fa = __half22float2(pa[e]);
            float2 fb = __half22float2(pb[e]);
            q[e * 2] = fa.x; q[e * 2 + 1] = fa.y;
            q[8 + e * 2] = fb.x; q[8 + e * 2 + 1] = fb.y;
        }
    }

    float sc[12];
    float mx = -1e30f;
    #pragma unroll
    for (int j = 0; j < 12; j++) {
        uint4 ka = *(const uint4*)(sp + j * 384 + 128 + h * 16);
        uint4 kb = *(const uint4*)(sp + j * 384 + 128 + h * 16 + 8);
        const __half2* pa = (const __half2*)&ka;
        const __half2* pb = (const __half2*)&kb;
        float a = 0.f;
        #pragma unroll
        for (int e = 0; e < 4; e++) {
            float2 fa = __half22float2(pa[e]);
            float2 fb = __half22float2(pb[e]);
            a += q[e * 2] * fa.x + q[e * 2 + 1] * fa.y;
            a += q[8 + e * 2] * fb.x + q[8 + e * 2 + 1] * fb.y;
        }
        a *= 0.25f;
        if (w == 0 && (gi != (j < SHIFTSZ))) a -= 100.f;
        sc[j] = a;
        mx = fmaxf(mx, a);
    }
    float den = 0.f;
    #pragma unroll
    for (int j = 0; j < 12; j++) { sc[j] = __expf(sc[j] - mx); den += sc[j]; }
    const float inv = 1.f / den;

    float o[16];
    #pragma unroll
    for (int d = 0; d < 16; d++) o[d] = 0.f;
    #pragma unroll
    for (int j = 0; j < 12; j++) {
        const float p = sc[j] * inv;
        uint4 va = *(const uint4*)(sp + j * 384 + 256 + h * 16);
        uint4 vb = *(const uint4*)(sp + j * 384 + 256 + h * 16 + 8);
        const __half2* pa = (const __half2*)&va;
        const __half2* pb = (const __half2*)&vb;
        #pragma unroll
        for (int e = 0; e < 4; e++) {
            float2 fa = __half22float2(pa[e]);
            float2 fb = __half22float2(pb[e]);
            o[e * 2]     += p * fa.x; o[e * 2 + 1] += p * fa.y;
            o[8 + e * 2] += p * fb.x; o[8 + e * 2 + 1] += p * fb.y;
        }
    }

    __align__(16) __half hv[16];
    #pragma unroll
    for (int d = 0; d < 16; d++) hv[d] = __float2half_rn(o[d]);
    __half* dsto = g_attn + (base + i) * 128 + h * 16;
    *(uint4*)(dsto)     = *(uint4*)(hv);
    *(uint4*)(dsto + 8) = *(uint4*)(hv + 8);
}

// ---------------------------------------------------------------------------
extern "C" void kernel_launch(void* const* d_in, const int* in_sizes, int n_in,
                              void* d_out, int out_size)
{
    const float* x      = (const float*)d_in[0];
    const float* qkv_w  = (const float*)d_in[1];
    const float* qkv_b  = (const float*)d_in[2];
    const float* proj_w = (const float*)d_in[3];
    const float* proj_b = (const float*)d_in[4];
    const float* fc1_w  = (const float*)d_in[5];
    const float* fc1_b  = (const float*)d_in[6];
    const float* fc2_w  = (const float*)d_in[7];
    const float* fc2_b  = (const float*)d_in[8];
    const float* g1     = (const float*)d_in[9];
    const float* b1     = (const float*)d_in[10];
    const float* g2     = (const float*)d_in[11];
    const float* b2     = (const float*)d_in[12];
    float* out = (float*)d_out;

    const int SM128 = 2 * STAGE > EPI_B ? 2 * STAGE : EPI_B;   // 49152
    const int SM512 = 3 * STAGE;                                // 73728

    static bool attr_done = false;
    if (!attr_done) {
        cudaFuncSetAttribute(tc_gemm<0, 128>, cudaFuncAttributeMaxDynamicSharedMemorySize, SM128);
        cudaFuncSetAttribute(tc_gemm<1, 128>, cudaFuncAttributeMaxDynamicSharedMemorySize, SM128);
        cudaFuncSetAttribute(tc_gemm<2, 128>, cudaFuncAttributeMaxDynamicSharedMemorySize, SM128);
        cudaFuncSetAttribute(tc_gemm<3, 512>, cudaFuncAttributeMaxDynamicSharedMemorySize, SM512);
        attr_done = true;
    }

    const int MB = MTOK / 64; // 3060

    // 0) weight transpose to fp16 [N][K]; x gather/shift to fp16
    prep_w<<<(W_TOTAL + 255) / 256, 256>>>(qkv_w, proj_w, fc1_w, fc2_w);
    prep_x<<<MTOK / 8, 256>>>(x);
    // 1) QKV projection
    tc_gemm<0, 128><<<dim3(MB, 3), 256, SM128>>>(OFF_QKV, qkv_b, nullptr, x, nullptr, nullptr);
    // 2) windowed attention (2 windows per block)
    attn_kernel<<<BB * NNH * (NWIN / 2), 192>>>();
    // 3) proj + unshift + LN1 + residual(x)
    tc_gemm<1, 128><<<dim3(MB, 1), 256, SM128>>>(OFF_PROJ, proj_b, nullptr, x, g1, b1);
    // 4) fc1 + GELU
    tc_gemm<2, 128><<<dim3(MB, 4), 256, SM128>>>(OFF_FC1, fc1_b, nullptr, nullptr, nullptr, nullptr);
    // 5) fc2 + LN2 + residual(x1h) + scatter to (B,L,N,D)
    tc_gemm<3, 512><<<dim3(MB, 1), 256, SM512>>>(OFF_FC2, fc2_b, out, nullptr, g2, b2);
}